// round 7
// baseline (speedup 1.0000x reference)
#include <cuda_runtime.h>
#include <cuda_fp16.h>
#include <math.h>

#define DD 64
#define MAXN   50176
#define MAXNB  256
#define MAXNPAD (MAXNB * 256)
#define MAXR 256
#define MAXE 2097152
#define SXP 65                       // padded x-tile row stride (bank-conflict fix)

typedef unsigned long long ull;

// Scratch (static device globals — no allocation anywhere; BSS zero-initialized)
__device__ unsigned g_Xh[2 * MAXN * 32];  // half2 words; row = 32 half2 = 16 uint2
__device__ unsigned g_Rh[2 * MAXR * 32];
__device__ int   g_cnt[MAXNPAD];
__device__ int   g_lex[MAXNPAD];
__device__ int   g_bsum[MAXNB];
__device__ int   g_base[MAXNB];
__device__ int   g_rank[MAXE];
__device__ uint2 g_pack2[MAXE];           // (x_row*16, r_row*16) uint2 offsets, CSR order
__device__ int   g_scanDone;
__device__ int   g_scanFlag;

__device__ __forceinline__ ull pack2f(float a, float b) {
    ull r;
    asm("mov.b64 %0, {%1, %2};" : "=l"(r) : "f"(a), "f"(b));
    return r;
}
__device__ __forceinline__ float2 unpack2f(ull v) {
    float2 r;
    asm("mov.b64 {%0, %1}, %2;" : "=f"(r.x), "=f"(r.y) : "l"(v));
    return r;
}
__device__ __forceinline__ void ffma2(ull& d, ull a, ull b) {
    asm("fma.rn.f32x2 %0, %1, %2, %0;" : "+l"(d) : "l"(a), "l"(b));
}

#define FSMEM (64 * 64 * 8 + 64 * SXP * 4)   // swp (32KB) + sx (16.6KB)

// ---------------------------------------------------------------------------
// K1: [histogram+rank] + [relation tables + r_out] + [node transform GEMM]
// ---------------------------------------------------------------------------
__global__ void __launch_bounds__(128) k_fused(
    const float* __restrict__ nf, const float* __restrict__ rf,
    const float* __restrict__ WI, const float* __restrict__ bI,
    const float* __restrict__ WO, const float* __restrict__ bO,
    const float* __restrict__ WR, const float* __restrict__ bR,
    float* __restrict__ r_out,
    const int* __restrict__ dst, int E,
    int N, int R, int nbH) {

    extern __shared__ __align__(16) unsigned char smem_raw[];
    ull*   swp = reinterpret_cast<ull*>(smem_raw);                  // [k*64 + p]
    float* sx  = reinterpret_cast<float*>(smem_raw + 64 * 64 * 8);  // [r*SXP + k]

    int b = blockIdx.x;
    int tid = threadIdx.x;

    if (b < nbH) {
        int t0 = (b * 128 + tid) * 8;
        if (t0 + 8 <= E) {
            int4 d0 = *reinterpret_cast<const int4*>(dst + t0);
            int4 d1 = *reinterpret_cast<const int4*>(dst + t0 + 4);
            int r0 = atomicAdd(&g_cnt[d0.x], 1);
            int r1 = atomicAdd(&g_cnt[d0.y], 1);
            int r2 = atomicAdd(&g_cnt[d0.z], 1);
            int r3 = atomicAdd(&g_cnt[d0.w], 1);
            int r4 = atomicAdd(&g_cnt[d1.x], 1);
            int r5 = atomicAdd(&g_cnt[d1.y], 1);
            int r6 = atomicAdd(&g_cnt[d1.z], 1);
            int r7 = atomicAdd(&g_cnt[d1.w], 1);
            *reinterpret_cast<int4*>(g_rank + t0)     = make_int4(r0, r1, r2, r3);
            *reinterpret_cast<int4*>(g_rank + t0 + 4) = make_int4(r4, r5, r6, r7);
        } else {
            for (int e = t0; e < E; e++)
                g_rank[e] = atomicAdd(&g_cnt[dst[e]], 1);
        }
        return;
    }
    b -= nbH;

    if (b < R) {
        // ---- relation tables (fp32 math, fp16 table store; r_out fp32) ----
        int t = b, j = tid;
        if (j < DD) sx[j] = rf[t * DD + j];
        __syncthreads();
        if (j < DD) {
            float aI = 0.f, aO = 0.f, aR = 0.f;
#pragma unroll 8
            for (int k = 0; k < DD; k++) {
                float v = sx[k];
                aI += v * WI[j * DD + k];
                aO += v * WO[j * DD + k];
                aR += v * WR[j * DD + k];
            }
            __half* Rh = reinterpret_cast<__half*>(g_Rh);
            Rh[t * DD + j]          = __float2half_rn(aI - bI[j]);
            Rh[(MAXR + t) * DD + j] = __float2half_rn(aO - bO[j]);
            r_out[t * DD + j]       = aR + bR[j];
        }
        return;
    }
    b -= R;

    // ---- node transform: 64-row tile -> 128 cols as 64 col-pairs (f32x2) ----
    int row0 = b * 64;

    for (int i = tid; i < 64 * 64; i += 128) {
        int p = i & 63;
        int k = i >> 6;
        float lo, hi;
        if (p < 32) { lo = WI[(2 * p) * 64 + k];       hi = WI[(2 * p + 1) * 64 + k]; }
        else { int q = p - 32; lo = WO[(2 * q) * 64 + k]; hi = WO[(2 * q + 1) * 64 + k]; }
        swp[k * 64 + p] = pack2f(lo, hi);
    }
    for (int i = tid; i < 64 * 16; i += 128) {
        int r  = i >> 4;
        int c4 = (i & 15) * 4;
        float4 v = make_float4(0.f, 0.f, 0.f, 0.f);
        int row = row0 + r;
        if (row < N) v = *reinterpret_cast<const float4*>(nf + (size_t)row * 64 + c4);
        sx[r * SXP + c4 + 0] = v.x;
        sx[r * SXP + c4 + 1] = v.y;
        sx[r * SXP + c4 + 2] = v.z;
        sx[r * SXP + c4 + 3] = v.w;
    }
    __syncthreads();

    int trow = tid >> 4;
    int tcol = tid & 15;
    int r0 = trow * 8;

    ull acc2[8][4];
#pragma unroll
    for (int i = 0; i < 8; i++)
#pragma unroll
        for (int jj = 0; jj < 4; jj++) acc2[i][jj] = 0ULL;

#pragma unroll 4
    for (int k = 0; k < 64; k++) {
        ull w2[4], a2[8];
#pragma unroll
        for (int jj = 0; jj < 4; jj++) w2[jj] = swp[k * 64 + tcol + 16 * jj];
#pragma unroll
        for (int i = 0; i < 8; i++) {
            float a = sx[(r0 + i) * SXP + k];
            a2[i] = pack2f(a, a);
        }
#pragma unroll
        for (int i = 0; i < 8; i++)
#pragma unroll
            for (int jj = 0; jj < 4; jj++) ffma2(acc2[i][jj], a2[i], w2[jj]);
    }

#pragma unroll
    for (int i = 0; i < 8; i++) {
        int row = row0 + r0 + i;
        if (row < N) {
#pragma unroll
            for (int jj = 0; jj < 4; jj++) {
                int p = tcol + 16 * jj;
                float2 f = unpack2f(acc2[i][jj]);
                __half2 h = __floats2half2_rn(f.x, f.y);
                unsigned hv = *reinterpret_cast<unsigned*>(&h);
                if (p < 32) g_Xh[(size_t)row * 32 + p]              = hv;
                else        g_Xh[(size_t)(N + row) * 32 + (p - 32)] = hv;
            }
        }
    }
}

// ---------------------------------------------------------------------------
// K2: fused [two-level exclusive scan] + [CSR reorder with flag handshake].
// Scan blocks (blockIdx < nbScan) all land in the deterministic first wave,
// so reorder blocks spinning cannot starve them.
// ---------------------------------------------------------------------------
__device__ __forceinline__ void reorder_one(int s, int d, int t, int r,
                                            int N, int half) {
    int pos = g_base[d >> 8] + g_lex[d] + r;
    unsigned row, trow;
    if (t < half) { row = (unsigned)s;       trow = (unsigned)t; }
    else          { row = (unsigned)(s + N); trow = (unsigned)(t + MAXR); }
    g_pack2[pos] = make_uint2(row * 16u, trow * 16u);   // prescaled uint2 offsets
}

__global__ void __launch_bounds__(256) k_scanreorder(
    const int* __restrict__ src, const int* __restrict__ dst,
    const int* __restrict__ et, int E, int N,
    const int* __restrict__ nrp, int halfFB, int nbScan) {

    __shared__ int s[256];
    __shared__ bool amLast;
    int t = threadIdx.x;
    int b = blockIdx.x;

    if (b < nbScan) {
        // ---- scan level 1 ----
        int i = b * 256 + t;
        int v = g_cnt[i];
        s[t] = v;
        __syncthreads();
#pragma unroll
        for (int off = 1; off < 256; off <<= 1) {
            int x = (t >= off) ? s[t - off] : 0;
            __syncthreads();
            s[t] += x;
            __syncthreads();
        }
        g_lex[i] = s[t] - v;
        if (t == 255) g_bsum[b] = s[t];
        __threadfence();
        if (t == 0) {
            int d = atomicAdd(&g_scanDone, 1);
            amLast = (d == nbScan - 1);
        }
        __syncthreads();
        if (amLast) {
            // ---- scan level 2 (last-arriving block) ----
            __threadfence();
            int v2 = (t < nbScan) ? g_bsum[t] : 0;
            s[t] = v2;
            __syncthreads();
#pragma unroll
            for (int off = 1; off < 256; off <<= 1) {
                int x = (t >= off) ? s[t - off] : 0;
                __syncthreads();
                s[t] += x;
                __syncthreads();
            }
            if (t < nbScan) g_base[t] = s[t] - v2;
            __threadfence();
            __syncthreads();
            if (t == 0) {
                g_scanDone = 0;                    // reset for next replay
                atomicExch(&g_scanFlag, 1);        // release
            }
        }
        return;
    }

    // ---- reorder part: prefetch edge data, wait for scan, scatter ----
    b -= nbScan;
    int i = b * 256 + t;
    int half = nrp ? (__ldg(nrp) >> 1) : halfFB;
    int main4 = E >> 2;

    int4 s4, d4, t4, r4;
    bool haveMain = (i < main4);
    if (haveMain) {
        s4 = reinterpret_cast<const int4*>(src)[i];
        d4 = reinterpret_cast<const int4*>(dst)[i];
        t4 = reinterpret_cast<const int4*>(et)[i];
        r4 = reinterpret_cast<const int4*>(g_rank)[i];
    }

    if (t == 0) {
        while (atomicAdd(&g_scanFlag, 0) == 0) __nanosleep(200);
    }
    __syncthreads();
    __threadfence();   // acquire: make g_base/g_lex visible

    if (haveMain) {
        reorder_one(s4.x, d4.x, t4.x, r4.x, N, half);
        reorder_one(s4.y, d4.y, t4.y, r4.y, N, half);
        reorder_one(s4.z, d4.z, t4.z, r4.z, N, half);
        reorder_one(s4.w, d4.w, t4.w, r4.w, N, half);
    } else if (i == main4) {
        for (int e = main4 * 4; e < E; e++)
            reorder_one(src[e], dst[e], et[e], g_rank[e], N, half);
    }
}

// ---------------------------------------------------------------------------
// K3: gather + mean. 1 warp/node, 2 edges/wave (half-warp x uint2 fp16).
// HSUB2 diff in fp16, fp32 accumulate. Prescaled offsets kill index math.
// Epilogue resets g_cnt and g_scanFlag for the next replay.
// ---------------------------------------------------------------------------
__global__ void __launch_bounds__(256) k_gather(float* __restrict__ out, int N) {
    int gid = blockIdx.x * 256 + threadIdx.x;
    if (gid == 0) g_scanFlag = 0;    // reset for next replay
    int v = gid >> 5;
    if (v >= N) return;
    int lane = threadIdx.x & 31;
    int half = lane >> 4;
    int l16  = lane & 15;

    int start = g_base[v >> 8] + g_lex[v];
    int deg   = g_cnt[v];

    const uint2* __restrict__ pk2 = g_pack2 + start;
    const uint2* __restrict__ X2 = reinterpret_cast<const uint2*>(g_Xh);
    const uint2* __restrict__ R2 = reinterpret_cast<const uint2*>(g_Rh);

    float4 acc = make_float4(0.f, 0.f, 0.f, 0.f);
    int i = 0;
    for (; i + 8 <= deg; i += 8) {
#pragma unroll
        for (int u = 0; u < 4; u++) {
            uint2 p = __ldcg(&pk2[i + 2 * u + half]);
            uint2 x = __ldcg(&X2[p.x + l16]);
            uint2 r = R2[p.y + l16];
            __half2 d0 = __hsub2(*reinterpret_cast<const __half2*>(&x.x),
                                 *reinterpret_cast<const __half2*>(&r.x));
            __half2 d1 = __hsub2(*reinterpret_cast<const __half2*>(&x.y),
                                 *reinterpret_cast<const __half2*>(&r.y));
            float2 f0 = __half22float2(d0);
            float2 f1 = __half22float2(d1);
            acc.x += f0.x; acc.y += f0.y;
            acc.z += f1.x; acc.w += f1.y;
        }
    }
    for (; i < deg; i += 2) {
        if (i + half < deg) {
            uint2 p = __ldcg(&pk2[i + half]);
            uint2 x = __ldcg(&X2[p.x + l16]);
            uint2 r = R2[p.y + l16];
            __half2 d0 = __hsub2(*reinterpret_cast<const __half2*>(&x.x),
                                 *reinterpret_cast<const __half2*>(&r.x));
            __half2 d1 = __hsub2(*reinterpret_cast<const __half2*>(&x.y),
                                 *reinterpret_cast<const __half2*>(&r.y));
            float2 f0 = __half22float2(d0);
            float2 f1 = __half22float2(d1);
            acc.x += f0.x; acc.y += f0.y;
            acc.z += f1.x; acc.w += f1.y;
        }
    }
    acc.x += __shfl_xor_sync(0xffffffffu, acc.x, 16);
    acc.y += __shfl_xor_sync(0xffffffffu, acc.y, 16);
    acc.z += __shfl_xor_sync(0xffffffffu, acc.z, 16);
    acc.w += __shfl_xor_sync(0xffffffffu, acc.w, 16);

    if (half == 0) {
        float inv = 1.0f / (float)(deg > 1 ? deg : 1);
        reinterpret_cast<float4*>(out)[(size_t)v * 16 + l16] =
            make_float4(acc.x * inv, acc.y * inv, acc.z * inv, acc.w * inv);
    }
    if (lane == 0) g_cnt[v] = 0;
}

// ---------------------------------------------------------------------------
extern "C" void kernel_launch(void* const* d_in, const int* in_sizes, int n_in,
                              void* d_out, int out_size) {
    const float* nf = (const float*)d_in[0];
    const float* rf = (const float*)d_in[1];
    const float* WI = (const float*)d_in[2];
    const float* bI = (const float*)d_in[3];
    const float* WO = (const float*)d_in[4];
    const float* bO = (const float*)d_in[5];
    const float* WR = (const float*)d_in[6];
    const float* bR = (const float*)d_in[7];
    const int* src  = (const int*)d_in[8];
    const int* dst  = (const int*)d_in[9];
    const int* et   = (const int*)d_in[10];
    const int* nrp  = (n_in > 11) ? (const int*)d_in[11] : nullptr;

    int Dv = in_sizes[3];            // = 64
    int N  = in_sizes[0] / Dv;
    int R  = in_sizes[1] / Dv;
    int E  = in_sizes[8];
    float* out = (float*)d_out;
    float* r_out = out + (size_t)N * Dv;

    int nb   = (N + 255) / 256;
    int nbNT = (N + 63) / 64;
    int nbH  = (E + 1023) / 1024;
    int nbRe = (((E >> 2) + 1) + 255) / 256;

    static int attrSet = 0;
    if (!attrSet) {
        cudaFuncSetAttribute(k_fused, cudaFuncAttributeMaxDynamicSharedMemorySize,
                             FSMEM);
        attrSet = 1;
    }

    k_fused<<<nbH + R + nbNT, 128, FSMEM>>>(nf, rf, WI, bI, WO, bO, WR, bR,
                                            r_out, dst, E, N, R, nbH);
    k_scanreorder<<<nb + nbRe, 256>>>(src, dst, et, E, N, nrp, R / 2, nb);
    {
        long long threads = (long long)N * 32;
        k_gather<<<(int)((threads + 255) / 256), 256>>>(out, N);
    }
}

// round 8
// speedup vs baseline: 1.1661x; 1.1661x over previous
#include <cuda_runtime.h>
#include <cuda_fp16.h>
#include <math.h>

#define DD 64
#define MAXN   50176
#define MAXNB  256
#define MAXNPAD (MAXNB * 256)
#define MAXR 256
#define MAXE 2097152
#define SXTP 66                      // k-major x-tile row stride (even, conflict-safe)

typedef unsigned long long ull;

// Scratch (static device globals — no allocation anywhere; BSS zero-initialized)
__device__ unsigned g_Xh[2 * MAXN * 32];  // half2 words; row = 32 half2 = 16 uint2
__device__ unsigned g_Rh[2 * MAXR * 32];
__device__ int   g_cnt[MAXNPAD];
__device__ int   g_lex[MAXNPAD];
__device__ int   g_bsum[MAXNB];
__device__ int   g_base[MAXNB];
__device__ int   g_rank[MAXE];
__device__ uint2 g_pack2[MAXE];           // (x_row*16, r_row*16) offsets, CSR order
__device__ int   g_scanDone;
__device__ int   g_scanFlag;

__device__ __forceinline__ ull pack2f(float a, float b) {
    ull r;
    asm("mov.b64 %0, {%1, %2};" : "=l"(r) : "f"(a), "f"(b));
    return r;
}
__device__ __forceinline__ float2 unpack2f(ull v) {
    float2 r;
    asm("mov.b64 {%0, %1}, %2;" : "=f"(r.x), "=f"(r.y) : "l"(v));
    return r;
}
__device__ __forceinline__ void ffma2(ull& d, ull a, ull b) {
    asm("fma.rn.f32x2 %0, %1, %2, %0;" : "+l"(d) : "l"(a), "l"(b));
}

// smem: sw float[64*128] (32KB) + sxT float[64*SXTP] (16.9KB)
#define FSMEM (64 * 128 * 4 + 64 * SXTP * 4)

// ---------------------------------------------------------------------------
// K1: [node transform GEMM] then [relation tables] then [histogram+rank].
// GEMM blocks first (longest-processing-time scheduling).
// 256 threads/block.
// ---------------------------------------------------------------------------
__global__ void __launch_bounds__(256) k_fused(
    const float* __restrict__ nf, const float* __restrict__ rf,
    const float* __restrict__ WI, const float* __restrict__ bI,
    const float* __restrict__ WO, const float* __restrict__ bO,
    const float* __restrict__ WR, const float* __restrict__ bR,
    float* __restrict__ r_out,
    const int* __restrict__ dst, int E,
    int N, int R, int nbNT) {

    extern __shared__ __align__(16) unsigned char smem_raw[];
    float* sw  = reinterpret_cast<float*>(smem_raw);                 // [k*128 + c]
    float* sxT = reinterpret_cast<float*>(smem_raw + 64 * 128 * 4);  // [k*SXTP + r]

    int b = blockIdx.x;
    int tid = threadIdx.x;

    if (b < nbNT) {
        // ================= node-transform GEMM: 64 rows x 128 cols =================
        int row0 = b * 64;

        // --- weights: coalesced-ish float4 row reads, conflict-free transposed STS
        // sw[k*128 + c] = (c<64) ? WI[c][k] : WO[c-64][k]
        for (int i = tid; i < 64 * 16; i += 256) {
            int j  = i & 63;           // output col within W
            int k4 = (i >> 6) * 4;     // input-dim group
            float4 vI = *reinterpret_cast<const float4*>(WI + j * 64 + k4);
            float4 vO = *reinterpret_cast<const float4*>(WO + j * 64 + k4);
            sw[(k4 + 0) * 128 + j] = vI.x;
            sw[(k4 + 1) * 128 + j] = vI.y;
            sw[(k4 + 2) * 128 + j] = vI.z;
            sw[(k4 + 3) * 128 + j] = vI.w;
            sw[(k4 + 0) * 128 + 64 + j] = vO.x;
            sw[(k4 + 1) * 128 + 64 + j] = vO.y;
            sw[(k4 + 2) * 128 + 64 + j] = vO.z;
            sw[(k4 + 3) * 128 + 64 + j] = vO.w;
        }
        // --- x tile, k-major: sxT[k*SXTP + r]
        for (int i = tid; i < 64 * 16; i += 256) {
            int r  = i & 63;
            int c4 = (i >> 6) * 4;
            float4 v = make_float4(0.f, 0.f, 0.f, 0.f);
            int row = row0 + r;
            if (row < N) v = *reinterpret_cast<const float4*>(nf + (size_t)row * 64 + c4);
            sxT[(c4 + 0) * SXTP + r] = v.x;
            sxT[(c4 + 1) * SXTP + r] = v.y;
            sxT[(c4 + 2) * SXTP + r] = v.z;
            sxT[(c4 + 3) * SXTP + r] = v.w;
        }
        __syncthreads();

        int tcol = tid & 15;          // col-pair group
        int trow = tid >> 4;          // 0..15
        int r0 = trow * 4;

        ull acc2[4][4];
#pragma unroll
        for (int i = 0; i < 4; i++)
#pragma unroll
            for (int j = 0; j < 4; j++) acc2[i][j] = 0ULL;

#pragma unroll 4
        for (int k = 0; k < 64; k++) {
            // w pairs: cols (2*(tcol+16j), 2*(tcol+16j)+1) — LDS.64, conflict-free
            ull w2[4];
#pragma unroll
            for (int j = 0; j < 4; j++)
                w2[j] = *reinterpret_cast<const ull*>(&sw[k * 128 + tcol * 2 + 32 * j]);
            // a: rows r0..r0+3 (2x LDS.64, broadcast across tcol)
            float2 aLo = *reinterpret_cast<const float2*>(&sxT[k * SXTP + r0]);
            float2 aHi = *reinterpret_cast<const float2*>(&sxT[k * SXTP + r0 + 2]);
            ull a2[4];
            a2[0] = pack2f(aLo.x, aLo.x);
            a2[1] = pack2f(aLo.y, aLo.y);
            a2[2] = pack2f(aHi.x, aHi.x);
            a2[3] = pack2f(aHi.y, aHi.y);
#pragma unroll
            for (int i = 0; i < 4; i++)
#pragma unroll
                for (int j = 0; j < 4; j++) ffma2(acc2[i][j], a2[i], w2[j]);
        }

        // epilogue: each acc2[i][j] = adjacent col pair -> one half2 word
#pragma unroll
        for (int i = 0; i < 4; i++) {
            int row = row0 + r0 + i;
            if (row < N) {
#pragma unroll
                for (int j = 0; j < 4; j++) {
                    int c = tcol + 16 * j;          // half2 word index, 0..63
                    float2 f = unpack2f(acc2[i][j]);
                    __half2 h = __floats2half2_rn(f.x, f.y);
                    unsigned hv = *reinterpret_cast<unsigned*>(&h);
                    if (c < 32) g_Xh[(size_t)row * 32 + c]              = hv;
                    else        g_Xh[(size_t)(N + row) * 32 + (c - 32)] = hv;
                }
            }
        }
        return;
    }
    b -= nbNT;

    if (b < R) {
        // ================= relation tables (fp32 math, fp16 store) =================
        int t = b, j = tid;
        if (j < DD) sxT[j] = rf[t * DD + j];
        __syncthreads();
        if (j < DD) {
            float aI = 0.f, aO = 0.f, aR = 0.f;
#pragma unroll 8
            for (int k = 0; k < DD; k++) {
                float v = sxT[k];
                aI += v * WI[j * DD + k];
                aO += v * WO[j * DD + k];
                aR += v * WR[j * DD + k];
            }
            __half* Rh = reinterpret_cast<__half*>(g_Rh);
            Rh[t * DD + j]          = __float2half_rn(aI - bI[j]);
            Rh[(MAXR + t) * DD + j] = __float2half_rn(aO - bO[j]);
            r_out[t * DD + j]       = aR + bR[j];
        }
        return;
    }
    b -= R;

    // ================= histogram + rank: 8 edges/thread =================
    {
        int t0 = (b * 256 + tid) * 8;
        if (t0 + 8 <= E) {
            int4 d0 = *reinterpret_cast<const int4*>(dst + t0);
            int4 d1 = *reinterpret_cast<const int4*>(dst + t0 + 4);
            int r0 = atomicAdd(&g_cnt[d0.x], 1);
            int r1 = atomicAdd(&g_cnt[d0.y], 1);
            int r2 = atomicAdd(&g_cnt[d0.z], 1);
            int r3 = atomicAdd(&g_cnt[d0.w], 1);
            int r4 = atomicAdd(&g_cnt[d1.x], 1);
            int r5 = atomicAdd(&g_cnt[d1.y], 1);
            int r6 = atomicAdd(&g_cnt[d1.z], 1);
            int r7 = atomicAdd(&g_cnt[d1.w], 1);
            *reinterpret_cast<int4*>(g_rank + t0)     = make_int4(r0, r1, r2, r3);
            *reinterpret_cast<int4*>(g_rank + t0 + 4) = make_int4(r4, r5, r6, r7);
        } else {
            for (int e = t0; e < E; e++)
                g_rank[e] = atomicAdd(&g_cnt[dst[e]], 1);
        }
    }
}

// ---------------------------------------------------------------------------
// K2: fused [two-level exclusive scan] + [CSR reorder with flag handshake].
// ---------------------------------------------------------------------------
__device__ __forceinline__ void reorder_one(int s, int d, int t, int r,
                                            int N, int half) {
    int pos = g_base[d >> 8] + g_lex[d] + r;
    unsigned row, trow;
    if (t < half) { row = (unsigned)s;       trow = (unsigned)t; }
    else          { row = (unsigned)(s + N); trow = (unsigned)(t + MAXR); }
    g_pack2[pos] = make_uint2(row * 16u, trow * 16u);
}

__global__ void __launch_bounds__(256) k_scanreorder(
    const int* __restrict__ src, const int* __restrict__ dst,
    const int* __restrict__ et, int E, int N,
    const int* __restrict__ nrp, int halfFB, int nbScan) {

    __shared__ int s[256];
    __shared__ bool amLast;
    int t = threadIdx.x;
    int b = blockIdx.x;

    if (b < nbScan) {
        int i = b * 256 + t;
        int v = g_cnt[i];
        s[t] = v;
        __syncthreads();
#pragma unroll
        for (int off = 1; off < 256; off <<= 1) {
            int x = (t >= off) ? s[t - off] : 0;
            __syncthreads();
            s[t] += x;
            __syncthreads();
        }
        g_lex[i] = s[t] - v;
        if (t == 255) g_bsum[b] = s[t];
        __threadfence();
        if (t == 0) {
            int d = atomicAdd(&g_scanDone, 1);
            amLast = (d == nbScan - 1);
        }
        __syncthreads();
        if (amLast) {
            __threadfence();
            int v2 = (t < nbScan) ? g_bsum[t] : 0;
            s[t] = v2;
            __syncthreads();
#pragma unroll
            for (int off = 1; off < 256; off <<= 1) {
                int x = (t >= off) ? s[t - off] : 0;
                __syncthreads();
                s[t] += x;
                __syncthreads();
            }
            if (t < nbScan) g_base[t] = s[t] - v2;
            __threadfence();
            __syncthreads();
            if (t == 0) {
                g_scanDone = 0;
                atomicExch(&g_scanFlag, 1);
            }
        }
        return;
    }

    b -= nbScan;
    int i = b * 256 + t;
    int half = nrp ? (__ldg(nrp) >> 1) : halfFB;
    int main4 = E >> 2;

    int4 s4, d4, t4, r4;
    bool haveMain = (i < main4);
    if (haveMain) {
        s4 = reinterpret_cast<const int4*>(src)[i];
        d4 = reinterpret_cast<const int4*>(dst)[i];
        t4 = reinterpret_cast<const int4*>(et)[i];
        r4 = reinterpret_cast<const int4*>(g_rank)[i];
    }

    if (t == 0) {
        while (atomicAdd(&g_scanFlag, 0) == 0) __nanosleep(200);
    }
    __syncthreads();
    __threadfence();

    if (haveMain) {
        reorder_one(s4.x, d4.x, t4.x, r4.x, N, half);
        reorder_one(s4.y, d4.y, t4.y, r4.y, N, half);
        reorder_one(s4.z, d4.z, t4.z, r4.z, N, half);
        reorder_one(s4.w, d4.w, t4.w, r4.w, N, half);
    } else if (i == main4) {
        for (int e = main4 * 4; e < E; e++)
            reorder_one(src[e], dst[e], et[e], g_rank[e], N, half);
    }
}

// ---------------------------------------------------------------------------
// K3: gather + mean (fp16 HSUB2, fp32 accumulate, prescaled offsets).
// ---------------------------------------------------------------------------
__global__ void __launch_bounds__(256) k_gather(float* __restrict__ out, int N) {
    int gid = blockIdx.x * 256 + threadIdx.x;
    if (gid == 0) g_scanFlag = 0;
    int v = gid >> 5;
    if (v >= N) return;
    int lane = threadIdx.x & 31;
    int half = lane >> 4;
    int l16  = lane & 15;

    int start = g_base[v >> 8] + g_lex[v];
    int deg   = g_cnt[v];

    const uint2* __restrict__ pk2 = g_pack2 + start;
    const uint2* __restrict__ X2 = reinterpret_cast<const uint2*>(g_Xh);
    const uint2* __restrict__ R2 = reinterpret_cast<const uint2*>(g_Rh);

    float4 acc = make_float4(0.f, 0.f, 0.f, 0.f);
    int i = 0;
    for (; i + 8 <= deg; i += 8) {
#pragma unroll
        for (int u = 0; u < 4; u++) {
            uint2 p = __ldcg(&pk2[i + 2 * u + half]);
            uint2 x = __ldcg(&X2[p.x + l16]);
            uint2 r = R2[p.y + l16];
            __half2 d0 = __hsub2(*reinterpret_cast<const __half2*>(&x.x),
                                 *reinterpret_cast<const __half2*>(&r.x));
            __half2 d1 = __hsub2(*reinterpret_cast<const __half2*>(&x.y),
                                 *reinterpret_cast<const __half2*>(&r.y));
            float2 f0 = __half22float2(d0);
            float2 f1 = __half22float2(d1);
            acc.x += f0.x; acc.y += f0.y;
            acc.z += f1.x; acc.w += f1.y;
        }
    }
    for (; i < deg; i += 2) {
        if (i + half < deg) {
            uint2 p = __ldcg(&pk2[i + half]);
            uint2 x = __ldcg(&X2[p.x + l16]);
            uint2 r = R2[p.y + l16];
            __half2 d0 = __hsub2(*reinterpret_cast<const __half2*>(&x.x),
                                 *reinterpret_cast<const __half2*>(&r.x));
            __half2 d1 = __hsub2(*reinterpret_cast<const __half2*>(&x.y),
                                 *reinterpret_cast<const __half2*>(&r.y));
            float2 f0 = __half22float2(d0);
            float2 f1 = __half22float2(d1);
            acc.x += f0.x; acc.y += f0.y;
            acc.z += f1.x; acc.w += f1.y;
        }
    }
    acc.x += __shfl_xor_sync(0xffffffffu, acc.x, 16);
    acc.y += __shfl_xor_sync(0xffffffffu, acc.y, 16);
    acc.z += __shfl_xor_sync(0xffffffffu, acc.z, 16);
    acc.w += __shfl_xor_sync(0xffffffffu, acc.w, 16);

    if (half == 0) {
        float inv = 1.0f / (float)(deg > 1 ? deg : 1);
        reinterpret_cast<float4*>(out)[(size_t)v * 16 + l16] =
            make_float4(acc.x * inv, acc.y * inv, acc.z * inv, acc.w * inv);
    }
    if (lane == 0) g_cnt[v] = 0;
}

// ---------------------------------------------------------------------------
extern "C" void kernel_launch(void* const* d_in, const int* in_sizes, int n_in,
                              void* d_out, int out_size) {
    const float* nf = (const float*)d_in[0];
    const float* rf = (const float*)d_in[1];
    const float* WI = (const float*)d_in[2];
    const float* bI = (const float*)d_in[3];
    const float* WO = (const float*)d_in[4];
    const float* bO = (const float*)d_in[5];
    const float* WR = (const float*)d_in[6];
    const float* bR = (const float*)d_in[7];
    const int* src  = (const int*)d_in[8];
    const int* dst  = (const int*)d_in[9];
    const int* et   = (const int*)d_in[10];
    const int* nrp  = (n_in > 11) ? (const int*)d_in[11] : nullptr;

    int Dv = in_sizes[3];            // = 64
    int N  = in_sizes[0] / Dv;
    int R  = in_sizes[1] / Dv;
    int E  = in_sizes[8];
    float* out = (float*)d_out;
    float* r_out = out + (size_t)N * Dv;

    int nb   = (N + 255) / 256;
    int nbNT = (N + 63) / 64;
    int nbH  = (E + 2047) / 2048;    // 256 thr x 8 edges
    int nbRe = (((E >> 2) + 1) + 255) / 256;

    static int attrSet = 0;
    if (!attrSet) {
        cudaFuncSetAttribute(k_fused, cudaFuncAttributeMaxDynamicSharedMemorySize,
                             FSMEM);
        attrSet = 1;
    }

    k_fused<<<nbNT + R + nbH, 256, FSMEM>>>(nf, rf, WI, bI, WO, bO, WR, bR,
                                            r_out, dst, E, N, R, nbNT);
    k_scanreorder<<<nb + nbRe, 256>>>(src, dst, et, E, N, nrp, R / 2, nb);
    {
        long long threads = (long long)N * 32;
        k_gather<<<(int)((threads + 255) / 256), 256>>>(out, N);
    }
}

// round 9
// speedup vs baseline: 1.3587x; 1.1652x over previous
#include <cuda_runtime.h>
#include <cuda_fp16.h>
#include <mma.h>
#include <math.h>

using namespace nvcuda;

#define DD 64
#define MAXNB  256
#define MAXNPAD (MAXNB * 256)
#define MAXR 256
#define MAXE 2097152

typedef unsigned long long ull;

// Scratch (static device globals — no allocation anywhere; BSS zero-initialized)
__device__ unsigned g_Xh[2 * 50176 * 32]; // half2 words; row = 32 half2 = 16 uint2
__device__ unsigned g_Rh[2 * MAXR * 32];
__device__ int   g_cnt[MAXNPAD];
__device__ int   g_lex[MAXNPAD];
__device__ int   g_bsum[MAXNB];
__device__ int   g_base[MAXNB];
__device__ int   g_rank[MAXE];
__device__ uint2 g_pack2[MAXE];           // (x_row*16, r_row*16) offsets, CSR order
__device__ int   g_scanDone;
__device__ int   g_scanFlag;

// smem for GEMM: phase1 sA half[64][72] (9216B) + sB half[64][136] (17408B) = 26624B
//                phase2 sO float[64][132] (33792B)  -- overlaps phase1
#define LDA 72
#define LDB 136
#define LDO 132
#define FSMEM (64 * LDO * 4)

// ---------------------------------------------------------------------------
// K1: [node-transform GEMM via wmma] + [relation tables] + [histogram+rank]
// GEMM blocks first (LPT scheduling). 256 threads/block.
// ---------------------------------------------------------------------------
__global__ void __launch_bounds__(256) k_fused(
    const float* __restrict__ nf, const float* __restrict__ rf,
    const float* __restrict__ WI, const float* __restrict__ bI,
    const float* __restrict__ WO, const float* __restrict__ bO,
    const float* __restrict__ WR, const float* __restrict__ bR,
    float* __restrict__ r_out,
    const int* __restrict__ dst, int E,
    int N, int R, int nbNT) {

    extern __shared__ __align__(16) unsigned char smem_raw[];

    int b = blockIdx.x;
    int tid = threadIdx.x;

    if (b < nbNT) {
        // ============== node transform: 64 rows x 128 cols, wmma fp16 ==============
        __half* sA = reinterpret_cast<__half*>(smem_raw);                 // [r][k] ld=LDA
        __half* sB = reinterpret_cast<__half*>(smem_raw) + 64 * LDA;      // [k][c] ld=LDB
        float*  sO = reinterpret_cast<float*>(smem_raw);                  // [r][c] ld=LDO

        int row0 = b * 64;

        // x tile -> fp16 smem (row-major [r][k])
        for (int i = tid; i < 64 * 16; i += 256) {
            int r  = i >> 4;
            int c4 = (i & 15) * 4;
            float4 v = make_float4(0.f, 0.f, 0.f, 0.f);
            int row = row0 + r;
            if (row < N) v = *reinterpret_cast<const float4*>(nf + (size_t)row * 64 + c4);
            __half2 h01 = __floats2half2_rn(v.x, v.y);
            __half2 h23 = __floats2half2_rn(v.z, v.w);
            *reinterpret_cast<__half2*>(&sA[r * LDA + c4])     = h01;
            *reinterpret_cast<__half2*>(&sA[r * LDA + c4 + 2]) = h23;
        }
        // weights -> fp16 smem transposed: sB[k][c] = (c<64 ? WI[c][k] : WO[c-64][k])
        for (int i = tid; i < 64 * 16; i += 256) {
            int c  = i & 63;
            int k4 = (i >> 6) * 4;
            float4 vI = *reinterpret_cast<const float4*>(WI + c * 64 + k4);
            float4 vO = *reinterpret_cast<const float4*>(WO + c * 64 + k4);
            sB[(k4 + 0) * LDB + c] = __float2half_rn(vI.x);
            sB[(k4 + 1) * LDB + c] = __float2half_rn(vI.y);
            sB[(k4 + 2) * LDB + c] = __float2half_rn(vI.z);
            sB[(k4 + 3) * LDB + c] = __float2half_rn(vI.w);
            sB[(k4 + 0) * LDB + 64 + c] = __float2half_rn(vO.x);
            sB[(k4 + 1) * LDB + 64 + c] = __float2half_rn(vO.y);
            sB[(k4 + 2) * LDB + 64 + c] = __float2half_rn(vO.z);
            sB[(k4 + 3) * LDB + 64 + c] = __float2half_rn(vO.w);
        }
        __syncthreads();

        // 8 warps: warp w -> rowT = w&3 (16 rows), colTs = (w>>2)*4 .. +3
        int w = tid >> 5;
        int rowT = w & 3;
        int colBase = (w >> 2) * 4;

        wmma::fragment<wmma::accumulator, 16, 16, 16, float> acc[4];
#pragma unroll
        for (int j = 0; j < 4; j++) wmma::fill_fragment(acc[j], 0.0f);

#pragma unroll
        for (int kt = 0; kt < 4; kt++) {
            wmma::fragment<wmma::matrix_a, 16, 16, 16, __half, wmma::row_major> fa;
            wmma::load_matrix_sync(fa, &sA[(rowT * 16) * LDA + kt * 16], LDA);
#pragma unroll
            for (int j = 0; j < 4; j++) {
                wmma::fragment<wmma::matrix_b, 16, 16, 16, __half, wmma::row_major> fb;
                wmma::load_matrix_sync(fb, &sB[(kt * 16) * LDB + (colBase + j) * 16], LDB);
                wmma::mma_sync(acc[j], fa, fb, acc[j]);
            }
        }

        __syncthreads();   // done reading sA/sB; sO overwrites them
#pragma unroll
        for (int j = 0; j < 4; j++)
            wmma::store_matrix_sync(&sO[(rowT * 16) * LDO + (colBase + j) * 16],
                                    acc[j], LDO, wmma::mem_row_major);
        __syncthreads();

        // writeout: 64 rows x 64 half2 words
        for (int i = tid; i < 64 * 64; i += 256) {
            int r  = i >> 6;
            int cw = i & 63;
            int row = row0 + r;
            if (row >= N) continue;
            float f0 = sO[r * LDO + cw * 2];
            float f1 = sO[r * LDO + cw * 2 + 1];
            __half2 h = __floats2half2_rn(f0, f1);
            unsigned hv = *reinterpret_cast<unsigned*>(&h);
            if (cw < 32) g_Xh[(size_t)row * 32 + cw]              = hv;
            else         g_Xh[(size_t)(N + row) * 32 + (cw - 32)] = hv;
        }
        return;
    }
    b -= nbNT;

    if (b < R) {
        // ================= relation tables (fp32 math, fp16 store) =================
        float* sf = reinterpret_cast<float*>(smem_raw);
        int t = b, j = tid;
        if (j < DD) sf[j] = rf[t * DD + j];
        __syncthreads();
        if (j < DD) {
            float aI = 0.f, aO = 0.f, aR = 0.f;
#pragma unroll 8
            for (int k = 0; k < DD; k++) {
                float v = sf[k];
                aI += v * WI[j * DD + k];
                aO += v * WO[j * DD + k];
                aR += v * WR[j * DD + k];
            }
            __half* Rh = reinterpret_cast<__half*>(g_Rh);
            Rh[t * DD + j]          = __float2half_rn(aI - bI[j]);
            Rh[(MAXR + t) * DD + j] = __float2half_rn(aO - bO[j]);
            r_out[t * DD + j]       = aR + bR[j];
        }
        return;
    }
    b -= R;

    // ================= histogram + rank: 8 edges/thread =================
    {
        int t0 = (b * 256 + tid) * 8;
        if (t0 + 8 <= E) {
            int4 d0 = *reinterpret_cast<const int4*>(dst + t0);
            int4 d1 = *reinterpret_cast<const int4*>(dst + t0 + 4);
            int r0 = atomicAdd(&g_cnt[d0.x], 1);
            int r1 = atomicAdd(&g_cnt[d0.y], 1);
            int r2 = atomicAdd(&g_cnt[d0.z], 1);
            int r3 = atomicAdd(&g_cnt[d0.w], 1);
            int r4 = atomicAdd(&g_cnt[d1.x], 1);
            int r5 = atomicAdd(&g_cnt[d1.y], 1);
            int r6 = atomicAdd(&g_cnt[d1.z], 1);
            int r7 = atomicAdd(&g_cnt[d1.w], 1);
            *reinterpret_cast<int4*>(g_rank + t0)     = make_int4(r0, r1, r2, r3);
            *reinterpret_cast<int4*>(g_rank + t0 + 4) = make_int4(r4, r5, r6, r7);
        } else {
            for (int e = t0; e < E; e++)
                g_rank[e] = atomicAdd(&g_cnt[dst[e]], 1);
        }
    }
}

// ---------------------------------------------------------------------------
// K2: fused [two-level exclusive scan] + [CSR reorder with flag handshake].
// ---------------------------------------------------------------------------
__device__ __forceinline__ void reorder_one(int s, int d, int t, int r,
                                            int N, int half) {
    int pos = g_base[d >> 8] + g_lex[d] + r;
    unsigned row, trow;
    if (t < half) { row = (unsigned)s;       trow = (unsigned)t; }
    else          { row = (unsigned)(s + N); trow = (unsigned)(t + MAXR); }
    g_pack2[pos] = make_uint2(row * 16u, trow * 16u);
}

__global__ void __launch_bounds__(256) k_scanreorder(
    const int* __restrict__ src, const int* __restrict__ dst,
    const int* __restrict__ et, int E, int N,
    const int* __restrict__ nrp, int halfFB, int nbScan) {

    __shared__ int s[256];
    __shared__ bool amLast;
    int t = threadIdx.x;
    int b = blockIdx.x;

    if (b < nbScan) {
        int i = b * 256 + t;
        int v = g_cnt[i];
        s[t] = v;
        __syncthreads();
#pragma unroll
        for (int off = 1; off < 256; off <<= 1) {
            int x = (t >= off) ? s[t - off] : 0;
            __syncthreads();
            s[t] += x;
            __syncthreads();
        }
        g_lex[i] = s[t] - v;
        if (t == 255) g_bsum[b] = s[t];
        __threadfence();
        if (t == 0) {
            int d = atomicAdd(&g_scanDone, 1);
            amLast = (d == nbScan - 1);
        }
        __syncthreads();
        if (amLast) {
            __threadfence();
            int v2 = (t < nbScan) ? g_bsum[t] : 0;
            s[t] = v2;
            __syncthreads();
#pragma unroll
            for (int off = 1; off < 256; off <<= 1) {
                int x = (t >= off) ? s[t - off] : 0;
                __syncthreads();
                s[t] += x;
                __syncthreads();
            }
            if (t < nbScan) g_base[t] = s[t] - v2;
            __threadfence();
            __syncthreads();
            if (t == 0) {
                g_scanDone = 0;
                atomicExch(&g_scanFlag, 1);
            }
        }
        return;
    }

    b -= nbScan;
    int i = b * 256 + t;
    int half = nrp ? (__ldg(nrp) >> 1) : halfFB;
    int main4 = E >> 2;

    int4 s4, d4, t4, r4;
    bool haveMain = (i < main4);
    if (haveMain) {
        s4 = reinterpret_cast<const int4*>(src)[i];
        d4 = reinterpret_cast<const int4*>(dst)[i];
        t4 = reinterpret_cast<const int4*>(et)[i];
        r4 = reinterpret_cast<const int4*>(g_rank)[i];
    }

    if (t == 0) {
        while (atomicAdd(&g_scanFlag, 0) == 0) __nanosleep(200);
    }
    __syncthreads();
    __threadfence();

    if (haveMain) {
        reorder_one(s4.x, d4.x, t4.x, r4.x, N, half);
        reorder_one(s4.y, d4.y, t4.y, r4.y, N, half);
        reorder_one(s4.z, d4.z, t4.z, r4.z, N, half);
        reorder_one(s4.w, d4.w, t4.w, r4.w, N, half);
    } else if (i == main4) {
        for (int e = main4 * 4; e < E; e++)
            reorder_one(src[e], dst[e], et[e], g_rank[e], N, half);
    }
}

// ---------------------------------------------------------------------------
// K3: gather + mean (fp16 HSUB2, fp32 accumulate, prescaled offsets).
// ---------------------------------------------------------------------------
__global__ void __launch_bounds__(256) k_gather(float* __restrict__ out, int N) {
    int gid = blockIdx.x * 256 + threadIdx.x;
    if (gid == 0) g_scanFlag = 0;
    int v = gid >> 5;
    if (v >= N) return;
    int lane = threadIdx.x & 31;
    int half = lane >> 4;
    int l16  = lane & 15;

    int start = g_base[v >> 8] + g_lex[v];
    int deg   = g_cnt[v];

    const uint2* __restrict__ pk2 = g_pack2 + start;
    const uint2* __restrict__ X2 = reinterpret_cast<const uint2*>(g_Xh);
    const uint2* __restrict__ R2 = reinterpret_cast<const uint2*>(g_Rh);

    float4 acc = make_float4(0.f, 0.f, 0.f, 0.f);
    int i = 0;
    for (; i + 8 <= deg; i += 8) {
#pragma unroll
        for (int u = 0; u < 4; u++) {
            uint2 p = __ldcg(&pk2[i + 2 * u + half]);
            uint2 x = __ldcg(&X2[p.x + l16]);
            uint2 r = R2[p.y + l16];
            __half2 d0 = __hsub2(*reinterpret_cast<const __half2*>(&x.x),
                                 *reinterpret_cast<const __half2*>(&r.x));
            __half2 d1 = __hsub2(*reinterpret_cast<const __half2*>(&x.y),
                                 *reinterpret_cast<const __half2*>(&r.y));
            float2 f0 = __half22float2(d0);
            float2 f1 = __half22float2(d1);
            acc.x += f0.x; acc.y += f0.y;
            acc.z += f1.x; acc.w += f1.y;
        }
    }
    for (; i < deg; i += 2) {
        if (i + half < deg) {
            uint2 p = __ldcg(&pk2[i + half]);
            uint2 x = __ldcg(&X2[p.x + l16]);
            uint2 r = R2[p.y + l16];
            __half2 d0 = __hsub2(*reinterpret_cast<const __half2*>(&x.x),
                                 *reinterpret_cast<const __half2*>(&r.x));
            __half2 d1 = __hsub2(*reinterpret_cast<const __half2*>(&x.y),
                                 *reinterpret_cast<const __half2*>(&r.y));
            float2 f0 = __half22float2(d0);
            float2 f1 = __half22float2(d1);
            acc.x += f0.x; acc.y += f0.y;
            acc.z += f1.x; acc.w += f1.y;
        }
    }
    acc.x += __shfl_xor_sync(0xffffffffu, acc.x, 16);
    acc.y += __shfl_xor_sync(0xffffffffu, acc.y, 16);
    acc.z += __shfl_xor_sync(0xffffffffu, acc.z, 16);
    acc.w += __shfl_xor_sync(0xffffffffu, acc.w, 16);

    if (half == 0) {
        float inv = 1.0f / (float)(deg > 1 ? deg : 1);
        reinterpret_cast<float4*>(out)[(size_t)v * 16 + l16] =
            make_float4(acc.x * inv, acc.y * inv, acc.z * inv, acc.w * inv);
    }
    if (lane == 0) g_cnt[v] = 0;
}

// ---------------------------------------------------------------------------
extern "C" void kernel_launch(void* const* d_in, const int* in_sizes, int n_in,
                              void* d_out, int out_size) {
    const float* nf = (const float*)d_in[0];
    const float* rf = (const float*)d_in[1];
    const float* WI = (const float*)d_in[2];
    const float* bI = (const float*)d_in[3];
    const float* WO = (const float*)d_in[4];
    const float* bO = (const float*)d_in[5];
    const float* WR = (const float*)d_in[6];
    const float* bR = (const float*)d_in[7];
    const int* src  = (const int*)d_in[8];
    const int* dst  = (const int*)d_in[9];
    const int* et   = (const int*)d_in[10];
    const int* nrp  = (n_in > 11) ? (const int*)d_in[11] : nullptr;

    int Dv = in_sizes[3];            // = 64
    int N  = in_sizes[0] / Dv;
    int R  = in_sizes[1] / Dv;
    int E  = in_sizes[8];
    float* out = (float*)d_out;
    float* r_out = out + (size_t)N * Dv;

    int nb   = (N + 255) / 256;
    int nbNT = (N + 63) / 64;
    int nbH  = (E + 2047) / 2048;    // 256 thr x 8 edges
    int nbRe = (((E >> 2) + 1) + 255) / 256;

    static int attrSet = 0;
    if (!attrSet) {
        cudaFuncSetAttribute(k_fused, cudaFuncAttributeMaxDynamicSharedMemorySize,
                             FSMEM);
        attrSet = 1;
    }

    k_fused<<<nbNT + R + nbH, 256, FSMEM>>>(nf, rf, WI, bI, WO, bO, WR, bR,
                                            r_out, dst, E, N, R, nbNT);
    k_scanreorder<<<nb + nbRe, 256>>>(src, dst, et, E, N, nrp, R / 2, nb);
    {
        long long threads = (long long)N * 32;
        k_gather<<<(int)((threads + 255) / 256), 256>>>(out, N);
    }
}

// round 10
// speedup vs baseline: 1.4155x; 1.0418x over previous
#include <cuda_runtime.h>
#include <cuda_fp16.h>
#include <mma.h>
#include <math.h>

using namespace nvcuda;

#define DD 64
#define MAXNB  256
#define MAXNPAD (MAXNB * 256)
#define MAXR 256
#define MAXE 2097152

typedef unsigned long long ull;

// Scratch (static device globals — no allocation anywhere; BSS zero-initialized)
__device__ unsigned g_Xh[2 * 50176 * 32]; // half2 words; row = 32 half2 = 16 uint2
__device__ unsigned g_Rh[2 * MAXR * 32];
__device__ int   g_cnt[MAXNPAD];
__device__ int   g_lex[MAXNPAD];
__device__ int   g_bsum[MAXNB];
__device__ int   g_base[MAXNB];
__device__ int   g_rank[MAXE];
__device__ uint2 g_pack2[MAXE];           // (x_row*16, r_row*16) offsets, CSR order
__device__ int   g_scanDone;
__device__ int   g_scanFlag;

// smem: sA half[64][72] (9216B) + sB half[64][136] (17408B)
//       + per-warp f32 scratch 8 x 16x20 (10240B)  = 36864B
#define LDA 72
#define LDB 136
#define LDW 20
#define SA_BYTES (64 * LDA * 2)
#define SB_BYTES (64 * LDB * 2)
#define FSMEM (SA_BYTES + SB_BYTES + 8 * 16 * LDW * 4)

// ---------------------------------------------------------------------------
// K1: [node-transform GEMM via wmma] + [relation tables] + [histogram+rank]
// GEMM blocks first (LPT scheduling). 256 threads/block, 4 blocks/SM target.
// ---------------------------------------------------------------------------
__global__ void __launch_bounds__(256, 4) k_fused(
    const float* __restrict__ nf, const float* __restrict__ rf,
    const float* __restrict__ WI, const float* __restrict__ bI,
    const float* __restrict__ WO, const float* __restrict__ bO,
    const float* __restrict__ WR, const float* __restrict__ bR,
    float* __restrict__ r_out,
    const int* __restrict__ dst, int E,
    int N, int R, int nbNT) {

    extern __shared__ __align__(16) unsigned char smem_raw[];

    int b = blockIdx.x;
    int tid = threadIdx.x;

    if (b < nbNT) {
        // ============== node transform: 64 rows x 128 cols, wmma fp16 ==============
        __half* sA = reinterpret_cast<__half*>(smem_raw);             // [r][k] ld=LDA
        __half* sB = reinterpret_cast<__half*>(smem_raw + SA_BYTES);  // [k][c] ld=LDB

        int row0 = b * 64;

        // x tile -> fp16 smem (row-major [r][k])
        for (int i = tid; i < 64 * 16; i += 256) {
            int r  = i >> 4;
            int c4 = (i & 15) * 4;
            float4 v = make_float4(0.f, 0.f, 0.f, 0.f);
            int row = row0 + r;
            if (row < N) v = *reinterpret_cast<const float4*>(nf + (size_t)row * 64 + c4);
            __half2 h01 = __floats2half2_rn(v.x, v.y);
            __half2 h23 = __floats2half2_rn(v.z, v.w);
            *reinterpret_cast<__half2*>(&sA[r * LDA + c4])     = h01;
            *reinterpret_cast<__half2*>(&sA[r * LDA + c4 + 2]) = h23;
        }
        // weights -> fp16 smem transposed: sB[k][c] = (c<64 ? WI[c][k] : WO[c-64][k])
        for (int i = tid; i < 64 * 16; i += 256) {
            int c  = i & 63;
            int k4 = (i >> 6) * 4;
            float4 vI = *reinterpret_cast<const float4*>(WI + c * 64 + k4);
            float4 vO = *reinterpret_cast<const float4*>(WO + c * 64 + k4);
            sB[(k4 + 0) * LDB + c] = __float2half_rn(vI.x);
            sB[(k4 + 1) * LDB + c] = __float2half_rn(vI.y);
            sB[(k4 + 2) * LDB + c] = __float2half_rn(vI.z);
            sB[(k4 + 3) * LDB + c] = __float2half_rn(vI.w);
            sB[(k4 + 0) * LDB + 64 + c] = __float2half_rn(vO.x);
            sB[(k4 + 1) * LDB + 64 + c] = __float2half_rn(vO.y);
            sB[(k4 + 2) * LDB + 64 + c] = __float2half_rn(vO.z);
            sB[(k4 + 3) * LDB + 64 + c] = __float2half_rn(vO.w);
        }
        __syncthreads();   // the ONLY block barrier in the GEMM path

        // 8 warps: warp w -> rowT = w&3 (16 rows), colTs = (w>>2)*4 .. +3
        int w = tid >> 5;
        int lane = tid & 31;
        int rowT = w & 3;
        int colBase = (w >> 2) * 4;

        wmma::fragment<wmma::accumulator, 16, 16, 16, float> acc[4];
#pragma unroll
        for (int j = 0; j < 4; j++) wmma::fill_fragment(acc[j], 0.0f);

#pragma unroll
        for (int kt = 0; kt < 4; kt++) {
            wmma::fragment<wmma::matrix_a, 16, 16, 16, __half, wmma::row_major> fa;
            wmma::load_matrix_sync(fa, &sA[(rowT * 16) * LDA + kt * 16], LDA);
#pragma unroll
            for (int j = 0; j < 4; j++) {
                wmma::fragment<wmma::matrix_b, 16, 16, 16, __half, wmma::row_major> fb;
                wmma::load_matrix_sync(fb, &sB[(kt * 16) * LDB + (colBase + j) * 16], LDB);
                wmma::mma_sync(acc[j], fa, fb, acc[j]);
            }
        }

        // warp-private epilogue: acc tile -> 16x20 f32 scratch -> half2 -> STG
        float* swarp = reinterpret_cast<float*>(smem_raw + SA_BYTES + SB_BYTES)
                       + w * (16 * LDW);
#pragma unroll
        for (int j = 0; j < 4; j++) {
            wmma::store_matrix_sync(swarp, acc[j], LDW, wmma::mem_row_major);
            __syncwarp();
            int c0w = (colBase + j) * 8;   // global half2-word base of this col tile
#pragma unroll
            for (int q = 0; q < 4; q++) {
                int idx = lane + 32 * q;   // 0..127 float2 index in 16x16 tile
                int r  = idx >> 3;
                int c2 = idx & 7;
                float2 f = *reinterpret_cast<const float2*>(&swarp[r * LDW + c2 * 2]);
                int row = row0 + rowT * 16 + r;
                if (row < N) {
                    __half2 h = __floats2half2_rn(f.x, f.y);
                    unsigned hv = *reinterpret_cast<unsigned*>(&h);
                    int cw = c0w + c2;
                    if (cw < 32) g_Xh[(size_t)row * 32 + cw]              = hv;
                    else         g_Xh[(size_t)(N + row) * 32 + (cw - 32)] = hv;
                }
            }
            __syncwarp();   // before next store_matrix_sync reuses swarp
        }
        return;
    }
    b -= nbNT;

    if (b < R) {
        // ================= relation tables (fp32 math, fp16 store) =================
        float* sf = reinterpret_cast<float*>(smem_raw);
        int t = b, j = tid;
        if (j < DD) sf[j] = rf[t * DD + j];
        __syncthreads();
        if (j < DD) {
            float aI = 0.f, aO = 0.f, aR = 0.f;
#pragma unroll 8
            for (int k = 0; k < DD; k++) {
                float v = sf[k];
                aI += v * WI[j * DD + k];
                aO += v * WO[j * DD + k];
                aR += v * WR[j * DD + k];
            }
            __half* Rh = reinterpret_cast<__half*>(g_Rh);
            Rh[t * DD + j]          = __float2half_rn(aI - bI[j]);
            Rh[(MAXR + t) * DD + j] = __float2half_rn(aO - bO[j]);
            r_out[t * DD + j]       = aR + bR[j];
        }
        return;
    }
    b -= R;

    // ================= histogram + rank: 8 edges/thread =================
    {
        int t0 = (b * 256 + tid) * 8;
        if (t0 + 8 <= E) {
            int4 d0 = *reinterpret_cast<const int4*>(dst + t0);
            int4 d1 = *reinterpret_cast<const int4*>(dst + t0 + 4);
            int r0 = atomicAdd(&g_cnt[d0.x], 1);
            int r1 = atomicAdd(&g_cnt[d0.y], 1);
            int r2 = atomicAdd(&g_cnt[d0.z], 1);
            int r3 = atomicAdd(&g_cnt[d0.w], 1);
            int r4 = atomicAdd(&g_cnt[d1.x], 1);
            int r5 = atomicAdd(&g_cnt[d1.y], 1);
            int r6 = atomicAdd(&g_cnt[d1.z], 1);
            int r7 = atomicAdd(&g_cnt[d1.w], 1);
            *reinterpret_cast<int4*>(g_rank + t0)     = make_int4(r0, r1, r2, r3);
            *reinterpret_cast<int4*>(g_rank + t0 + 4) = make_int4(r4, r5, r6, r7);
        } else {
            for (int e = t0; e < E; e++)
                g_rank[e] = atomicAdd(&g_cnt[dst[e]], 1);
        }
    }
}

// ---------------------------------------------------------------------------
// K2: fused [two-level exclusive scan] + [CSR reorder with flag handshake].
// ---------------------------------------------------------------------------
__device__ __forceinline__ void reorder_one(int s, int d, int t, int r,
                                            int N, int half) {
    int pos = g_base[d >> 8] + g_lex[d] + r;
    unsigned row, trow;
    if (t < half) { row = (unsigned)s;       trow = (unsigned)t; }
    else          { row = (unsigned)(s + N); trow = (unsigned)(t + MAXR); }
    g_pack2[pos] = make_uint2(row * 16u, trow * 16u);
}

__global__ void __launch_bounds__(256) k_scanreorder(
    const int* __restrict__ src, const int* __restrict__ dst,
    const int* __restrict__ et, int E, int N,
    const int* __restrict__ nrp, int halfFB, int nbScan) {

    __shared__ int s[256];
    __shared__ bool amLast;
    int t = threadIdx.x;
    int b = blockIdx.x;

    if (b < nbScan) {
        int i = b * 256 + t;
        int v = g_cnt[i];
        s[t] = v;
        __syncthreads();
#pragma unroll
        for (int off = 1; off < 256; off <<= 1) {
            int x = (t >= off) ? s[t - off] : 0;
            __syncthreads();
            s[t] += x;
            __syncthreads();
        }
        g_lex[i] = s[t] - v;
        if (t == 255) g_bsum[b] = s[t];
        __threadfence();
        if (t == 0) {
            int d = atomicAdd(&g_scanDone, 1);
            amLast = (d == nbScan - 1);
        }
        __syncthreads();
        if (amLast) {
            __threadfence();
            int v2 = (t < nbScan) ? g_bsum[t] : 0;
            s[t] = v2;
            __syncthreads();
#pragma unroll
            for (int off = 1; off < 256; off <<= 1) {
                int x = (t >= off) ? s[t - off] : 0;
                __syncthreads();
                s[t] += x;
                __syncthreads();
            }
            if (t < nbScan) g_base[t] = s[t] - v2;
            __threadfence();
            __syncthreads();
            if (t == 0) {
                g_scanDone = 0;
                atomicExch(&g_scanFlag, 1);
            }
        }
        return;
    }

    b -= nbScan;
    int i = b * 256 + t;
    int half = nrp ? (__ldg(nrp) >> 1) : halfFB;
    int main4 = E >> 2;

    int4 s4, d4, t4, r4;
    bool haveMain = (i < main4);
    if (haveMain) {
        s4 = reinterpret_cast<const int4*>(src)[i];
        d4 = reinterpret_cast<const int4*>(dst)[i];
        t4 = reinterpret_cast<const int4*>(et)[i];
        r4 = reinterpret_cast<const int4*>(g_rank)[i];
    }

    if (t == 0) {
        while (atomicAdd(&g_scanFlag, 0) == 0) __nanosleep(200);
    }
    __syncthreads();
    __threadfence();

    if (haveMain) {
        reorder_one(s4.x, d4.x, t4.x, r4.x, N, half);
        reorder_one(s4.y, d4.y, t4.y, r4.y, N, half);
        reorder_one(s4.z, d4.z, t4.z, r4.z, N, half);
        reorder_one(s4.w, d4.w, t4.w, r4.w, N, half);
    } else if (i == main4) {
        for (int e = main4 * 4; e < E; e++)
            reorder_one(src[e], dst[e], et[e], g_rank[e], N, half);
    }
}

// ---------------------------------------------------------------------------
// K3: gather + mean (fp16 HSUB2, fp32 accumulate, prescaled offsets).
// ---------------------------------------------------------------------------
__global__ void __launch_bounds__(256) k_gather(float* __restrict__ out, int N) {
    int gid = blockIdx.x * 256 + threadIdx.x;
    if (gid == 0) g_scanFlag = 0;
    int v = gid >> 5;
    if (v >= N) return;
    int lane = threadIdx.x & 31;
    int half = lane >> 4;
    int l16  = lane & 15;

    int start = g_base[v >> 8] + g_lex[v];
    int deg   = g_cnt[v];

    const uint2* __restrict__ pk2 = g_pack2 + start;
    const uint2* __restrict__ X2 = reinterpret_cast<const uint2*>(g_Xh);
    const uint2* __restrict__ R2 = reinterpret_cast<const uint2*>(g_Rh);

    float4 acc = make_float4(0.f, 0.f, 0.f, 0.f);
    int i = 0;
    for (; i + 8 <= deg; i += 8) {
#pragma unroll
        for (int u = 0; u < 4; u++) {
            uint2 p = __ldcg(&pk2[i + 2 * u + half]);
            uint2 x = __ldcg(&X2[p.x + l16]);
            uint2 r = R2[p.y + l16];
            __half2 d0 = __hsub2(*reinterpret_cast<const __half2*>(&x.x),
                                 *reinterpret_cast<const __half2*>(&r.x));
            __half2 d1 = __hsub2(*reinterpret_cast<const __half2*>(&x.y),
                                 *reinterpret_cast<const __half2*>(&r.y));
            float2 f0 = __half22float2(d0);
            float2 f1 = __half22float2(d1);
            acc.x += f0.x; acc.y += f0.y;
            acc.z += f1.x; acc.w += f1.y;
        }
    }
    for (; i < deg; i += 2) {
        if (i + half < deg) {
            uint2 p = __ldcg(&pk2[i + half]);
            uint2 x = __ldcg(&X2[p.x + l16]);
            uint2 r = R2[p.y + l16];
            __half2 d0 = __hsub2(*reinterpret_cast<const __half2*>(&x.x),
                                 *reinterpret_cast<const __half2*>(&r.x));
            __half2 d1 = __hsub2(*reinterpret_cast<const __half2*>(&x.y),
                                 *reinterpret_cast<const __half2*>(&r.y));
            float2 f0 = __half22float2(d0);
            float2 f1 = __half22float2(d1);
            acc.x += f0.x; acc.y += f0.y;
            acc.z += f1.x; acc.w += f1.y;
        }
    }
    acc.x += __shfl_xor_sync(0xffffffffu, acc.x, 16);
    acc.y += __shfl_xor_sync(0xffffffffu, acc.y, 16);
    acc.z += __shfl_xor_sync(0xffffffffu, acc.z, 16);
    acc.w += __shfl_xor_sync(0xffffffffu, acc.w, 16);

    if (half == 0) {
        float inv = 1.0f / (float)(deg > 1 ? deg : 1);
        reinterpret_cast<float4*>(out)[(size_t)v * 16 + l16] =
            make_float4(acc.x * inv, acc.y * inv, acc.z * inv, acc.w * inv);
    }
    if (lane == 0) g_cnt[v] = 0;
}

// ---------------------------------------------------------------------------
extern "C" void kernel_launch(void* const* d_in, const int* in_sizes, int n_in,
                              void* d_out, int out_size) {
    const float* nf = (const float*)d_in[0];
    const float* rf = (const float*)d_in[1];
    const float* WI = (const float*)d_in[2];
    const float* bI = (const float*)d_in[3];
    const float* WO = (const float*)d_in[4];
    const float* bO = (const float*)d_in[5];
    const float* WR = (const float*)d_in[6];
    const float* bR = (const float*)d_in[7];
    const int* src  = (const int*)d_in[8];
    const int* dst  = (const int*)d_in[9];
    const int* et   = (const int*)d_in[10];
    const int* nrp  = (n_in > 11) ? (const int*)d_in[11] : nullptr;

    int Dv = in_sizes[3];            // = 64
    int N  = in_sizes[0] / Dv;
    int R  = in_sizes[1] / Dv;
    int E  = in_sizes[8];
    float* out = (float*)d_out;
    float* r_out = out + (size_t)N * Dv;

    int nb   = (N + 255) / 256;
    int nbNT = (N + 63) / 64;
    int nbH  = (E + 2047) / 2048;    // 256 thr x 8 edges
    int nbRe = (((E >> 2) + 1) + 255) / 256;

    static int attrSet = 0;
    if (!attrSet) {
        cudaFuncSetAttribute(k_fused, cudaFuncAttributeMaxDynamicSharedMemorySize,
                             FSMEM);
        attrSet = 1;
    }

    k_fused<<<nbNT + R + nbH, 256, FSMEM>>>(nf, rf, WI, bI, WO, bO, WR, bR,
                                            r_out, dst, E, N, R, nbNT);
    k_scanreorder<<<nb + nbRe, 256>>>(src, dst, et, E, N, nrp, R / 2, nb);
    {
        long long threads = (long long)N * 32;
        k_gather<<<(int)((threads + 255) / 256), 256>>>(out, N);
    }
}

// round 11
// speedup vs baseline: 1.5362x; 1.0852x over previous
#include <cuda_runtime.h>
#include <cuda_fp16.h>
#include <mma.h>
#include <math.h>

using namespace nvcuda;

#define DD 64
#define MAXNB  256
#define MAXNPAD (MAXNB * 256)
#define MAXR 256
#define MAXE 2097152

// Scratch (static device globals — no allocation anywhere; BSS zero-initialized)
__device__ unsigned g_Xh[2 * 50176 * 32]; // half2 words; row = 32 half2 = 16 uint2
__device__ unsigned g_Rh[2 * MAXR * 32];
__device__ int   g_cnt[MAXNPAD];
__device__ int   g_lex[MAXNPAD];
__device__ int   g_bsum[MAXNB];
__device__ int   g_base[MAXNB];
__device__ int   g_rank[MAXE];
__device__ uint2 g_pack2[MAXE];           // (x_row*16, r_row*16) offsets, CSR order
__device__ int   g_scanDone;              // self-resetting
__device__ int   g_scanFlag;              // reset by gather
__device__ int   g_histDone;              // reset by gather

// smem: sA half[64][72] (9216B) + sB half[64][136] (17408B)
//       + per-warp f32 scratch 8 x 16x20 (10240B)  = 36864B
#define LDA 72
#define LDB 136
#define LDW 20
#define SA_BYTES (64 * LDA * 2)
#define SB_BYTES (64 * LDB * 2)
#define FSMEM (SA_BYTES + SB_BYTES + 8 * 16 * LDW * 4)

// ---------------------------------------------------------------------------
// K1 mega: [hist][scan][GEMM][rel][reorder] in one launch, overlapped via
// dispatch-order + counter/flag handshakes (monotone block dispatch).
// ---------------------------------------------------------------------------
__global__ void __launch_bounds__(256, 4) k_mega(
    const float* __restrict__ nf, const float* __restrict__ rf,
    const float* __restrict__ WI, const float* __restrict__ bI,
    const float* __restrict__ WO, const float* __restrict__ bO,
    const float* __restrict__ WR, const float* __restrict__ bR,
    float* __restrict__ r_out,
    const int* __restrict__ src, const int* __restrict__ dst,
    const int* __restrict__ et, const int* __restrict__ nrp,
    int E, int N, int R, int halfFB,
    int nbH, int nbScan, int nbNT) {

    extern __shared__ __align__(16) unsigned char smem_raw[];
    __shared__ int s[256];
    __shared__ bool amLast;

    int b = blockIdx.x;
    int tid = threadIdx.x;

    // ======================= phase 1: histogram + rank =======================
    if (b < nbH) {
        int t0 = (b * 256 + tid) * 8;
        if (t0 + 8 <= E) {
            int4 d0 = *reinterpret_cast<const int4*>(dst + t0);
            int4 d1 = *reinterpret_cast<const int4*>(dst + t0 + 4);
            int r0 = atomicAdd(&g_cnt[d0.x], 1);
            int r1 = atomicAdd(&g_cnt[d0.y], 1);
            int r2 = atomicAdd(&g_cnt[d0.z], 1);
            int r3 = atomicAdd(&g_cnt[d0.w], 1);
            int r4 = atomicAdd(&g_cnt[d1.x], 1);
            int r5 = atomicAdd(&g_cnt[d1.y], 1);
            int r6 = atomicAdd(&g_cnt[d1.z], 1);
            int r7 = atomicAdd(&g_cnt[d1.w], 1);
            *reinterpret_cast<int4*>(g_rank + t0)     = make_int4(r0, r1, r2, r3);
            *reinterpret_cast<int4*>(g_rank + t0 + 4) = make_int4(r4, r5, r6, r7);
        } else {
            for (int e = t0; e < E; e++)
                g_rank[e] = atomicAdd(&g_cnt[dst[e]], 1);
        }
        __threadfence();
        __syncthreads();
        if (tid == 0) atomicAdd(&g_histDone, 1);
        return;
    }
    b -= nbH;

    // ======================= phase 2: two-level scan =======================
    if (b < nbScan) {
        if (tid == 0) {
            while (atomicAdd(&g_histDone, 0) < nbH) __nanosleep(100);
        }
        __syncthreads();
        __threadfence();

        int i = b * 256 + tid;
        int v = g_cnt[i];
        s[tid] = v;
        __syncthreads();
#pragma unroll
        for (int off = 1; off < 256; off <<= 1) {
            int x = (tid >= off) ? s[tid - off] : 0;
            __syncthreads();
            s[tid] += x;
            __syncthreads();
        }
        g_lex[i] = s[tid] - v;
        if (tid == 255) g_bsum[b] = s[tid];
        __threadfence();
        if (tid == 0) {
            int d = atomicAdd(&g_scanDone, 1);
            amLast = (d == nbScan - 1);
        }
        __syncthreads();
        if (amLast) {
            __threadfence();
            int v2 = (tid < nbScan) ? g_bsum[tid] : 0;
            s[tid] = v2;
            __syncthreads();
#pragma unroll
            for (int off = 1; off < 256; off <<= 1) {
                int x = (tid >= off) ? s[tid - off] : 0;
                __syncthreads();
                s[tid] += x;
                __syncthreads();
            }
            if (tid < nbScan) g_base[tid] = s[tid] - v2;
            __threadfence();
            __syncthreads();
            if (tid == 0) {
                g_scanDone = 0;
                atomicExch(&g_scanFlag, 1);
            }
        }
        return;
    }
    b -= nbScan;

    // ======================= phase 3: node-transform GEMM =======================
    if (b < nbNT) {
        __half* sA = reinterpret_cast<__half*>(smem_raw);             // [r][k] ld=LDA
        __half* sB = reinterpret_cast<__half*>(smem_raw + SA_BYTES);  // [k][c] ld=LDB

        int row0 = b * 64;

        // x tile -> fp16 smem (row-major [r][k])
        for (int i = tid; i < 64 * 16; i += 256) {
            int r  = i >> 4;
            int c4 = (i & 15) * 4;
            float4 v = make_float4(0.f, 0.f, 0.f, 0.f);
            int row = row0 + r;
            if (row < N) v = *reinterpret_cast<const float4*>(nf + (size_t)row * 64 + c4);
            __half2 h01 = __floats2half2_rn(v.x, v.y);
            __half2 h23 = __floats2half2_rn(v.z, v.w);
            *reinterpret_cast<__half2*>(&sA[r * LDA + c4])     = h01;
            *reinterpret_cast<__half2*>(&sA[r * LDA + c4 + 2]) = h23;
        }
        // weights -> fp16 smem transposed, half2-packed (4 F2FP + 4 STS.32/iter)
        for (int i = tid; i < 64 * 16; i += 256) {
            int cw2 = i & 63;          // half2-word col 0..63
            int k4  = (i >> 6) * 4;    // k group
            const float* Wb = (cw2 < 32) ? WI : WO;
            int c0 = (cw2 & 31) * 2;
            float4 va = *reinterpret_cast<const float4*>(Wb + c0 * 64 + k4);
            float4 vb = *reinterpret_cast<const float4*>(Wb + (c0 + 1) * 64 + k4);
            *reinterpret_cast<__half2*>(&sB[(k4 + 0) * LDB + cw2 * 2]) = __floats2half2_rn(va.x, vb.x);
            *reinterpret_cast<__half2*>(&sB[(k4 + 1) * LDB + cw2 * 2]) = __floats2half2_rn(va.y, vb.y);
            *reinterpret_cast<__half2*>(&sB[(k4 + 2) * LDB + cw2 * 2]) = __floats2half2_rn(va.z, vb.z);
            *reinterpret_cast<__half2*>(&sB[(k4 + 3) * LDB + cw2 * 2]) = __floats2half2_rn(va.w, vb.w);
        }
        __syncthreads();

        int w = tid >> 5;
        int lane = tid & 31;
        int rowT = w & 3;
        int colBase = (w >> 2) * 4;

        wmma::fragment<wmma::accumulator, 16, 16, 16, float> acc[4];
#pragma unroll
        for (int j = 0; j < 4; j++) wmma::fill_fragment(acc[j], 0.0f);

#pragma unroll
        for (int kt = 0; kt < 4; kt++) {
            wmma::fragment<wmma::matrix_a, 16, 16, 16, __half, wmma::row_major> fa;
            wmma::load_matrix_sync(fa, &sA[(rowT * 16) * LDA + kt * 16], LDA);
#pragma unroll
            for (int j = 0; j < 4; j++) {
                wmma::fragment<wmma::matrix_b, 16, 16, 16, __half, wmma::row_major> fb;
                wmma::load_matrix_sync(fb, &sB[(kt * 16) * LDB + (colBase + j) * 16], LDB);
                wmma::mma_sync(acc[j], fa, fb, acc[j]);
            }
        }

        // warp-private epilogue; region branch uniform per tile; STG.64
        float* swarp = reinterpret_cast<float*>(smem_raw + SA_BYTES + SB_BYTES)
                       + w * (16 * LDW);
#pragma unroll
        for (int j = 0; j < 4; j++) {
            wmma::store_matrix_sync(swarp, acc[j], LDW, wmma::mem_row_major);
            __syncwarp();
            int c0w = (colBase + j) * 8;                 // multiple of 8
            unsigned* dstBase = (c0w < 32)
                ? g_Xh + c0w
                : g_Xh + (size_t)N * 32 + (c0w - 32);
#pragma unroll
            for (int q = 0; q < 2; q++) {
                int idx = lane + 32 * q;  // 0..63
                int r   = idx >> 2;
                int w2  = (idx & 3) * 2;  // word offset 0,2,4,6
                float4 f = *reinterpret_cast<const float4*>(&swarp[r * LDW + w2 * 2]);
                int row = row0 + rowT * 16 + r;
                if (row < N) {
                    __half2 h0 = __floats2half2_rn(f.x, f.y);
                    __half2 h1 = __floats2half2_rn(f.z, f.w);
                    uint2 hv = make_uint2(*reinterpret_cast<unsigned*>(&h0),
                                          *reinterpret_cast<unsigned*>(&h1));
                    *reinterpret_cast<uint2*>(dstBase + (size_t)row * 32 + w2) = hv;
                }
            }
            __syncwarp();
        }
        return;
    }
    b -= nbNT;

    // ======================= phase 4: relation tables =======================
    if (b < R) {
        float* sf = reinterpret_cast<float*>(smem_raw);
        int t = b, j = tid;
        if (j < DD) sf[j] = rf[t * DD + j];
        __syncthreads();
        if (j < DD) {
            float aI = 0.f, aO = 0.f, aR = 0.f;
#pragma unroll 8
            for (int k = 0; k < DD; k++) {
                float v = sf[k];
                aI += v * WI[j * DD + k];
                aO += v * WO[j * DD + k];
                aR += v * WR[j * DD + k];
            }
            __half* Rh = reinterpret_cast<__half*>(g_Rh);
            Rh[t * DD + j]          = __float2half_rn(aI - bI[j]);
            Rh[(MAXR + t) * DD + j] = __float2half_rn(aO - bO[j]);
            r_out[t * DD + j]       = aR + bR[j];
        }
        return;
    }
    b -= R;

    // ======================= phase 5: CSR reorder =======================
    {
        int i = b * 256 + tid;
        int half = nrp ? (__ldg(nrp) >> 1) : halfFB;
        int main4 = E >> 2;

        int4 s4, d4, t4;
        bool haveMain = (i < main4);
        if (haveMain) {
            s4 = reinterpret_cast<const int4*>(src)[i];
            d4 = reinterpret_cast<const int4*>(dst)[i];
            t4 = reinterpret_cast<const int4*>(et)[i];
        }

        if (tid == 0) {
            while (atomicAdd(&g_scanFlag, 0) == 0) __nanosleep(200);
        }
        __syncthreads();
        __threadfence();   // acquire: g_base/g_lex/g_rank now visible

        if (haveMain) {
            int4 r4 = reinterpret_cast<const int4*>(g_rank)[i];
#pragma unroll
            for (int u = 0; u < 4; u++) {
                int ss = (u == 0) ? s4.x : (u == 1) ? s4.y : (u == 2) ? s4.z : s4.w;
                int dd = (u == 0) ? d4.x : (u == 1) ? d4.y : (u == 2) ? d4.z : d4.w;
                int tt = (u == 0) ? t4.x : (u == 1) ? t4.y : (u == 2) ? t4.z : t4.w;
                int rr = (u == 0) ? r4.x : (u == 1) ? r4.y : (u == 2) ? r4.z : r4.w;
                int pos = g_base[dd >> 8] + g_lex[dd] + rr;
                unsigned row, trow;
                if (tt < half) { row = (unsigned)ss;       trow = (unsigned)tt; }
                else           { row = (unsigned)(ss + N); trow = (unsigned)(tt + MAXR); }
                g_pack2[pos] = make_uint2(row * 16u, trow * 16u);
            }
        } else if (i == main4) {
            for (int e = main4 * 4; e < E; e++) {
                int ss = src[e], dd = dst[e], tt = et[e], rr = g_rank[e];
                int pos = g_base[dd >> 8] + g_lex[dd] + rr;
                unsigned row, trow;
                if (tt < half) { row = (unsigned)ss;       trow = (unsigned)tt; }
                else           { row = (unsigned)(ss + N); trow = (unsigned)(tt + MAXR); }
                g_pack2[pos] = make_uint2(row * 16u, trow * 16u);
            }
        }
    }
}

// ---------------------------------------------------------------------------
// K2: gather + mean (fp16 HSUB2, fp32 accumulate, prescaled offsets).
// Resets histDone/scanFlag/g_cnt for the next replay.
// ---------------------------------------------------------------------------
__global__ void __launch_bounds__(256) k_gather(float* __restrict__ out, int N) {
    int gid = blockIdx.x * 256 + threadIdx.x;
    if (gid == 0) { g_scanFlag = 0; g_histDone = 0; }
    int v = gid >> 5;
    if (v >= N) return;
    int lane = threadIdx.x & 31;
    int half = lane >> 4;
    int l16  = lane & 15;

    int start = g_base[v >> 8] + g_lex[v];
    int deg   = g_cnt[v];

    const uint2* __restrict__ pk2 = g_pack2 + start;
    const uint2* __restrict__ X2 = reinterpret_cast<const uint2*>(g_Xh);
    const uint2* __restrict__ R2 = reinterpret_cast<const uint2*>(g_Rh);

    float4 acc = make_float4(0.f, 0.f, 0.f, 0.f);
    int i = 0;
    for (; i + 8 <= deg; i += 8) {
#pragma unroll
        for (int u = 0; u < 4; u++) {
            uint2 p = __ldcg(&pk2[i + 2 * u + half]);
            uint2 x = __ldcg(&X2[p.x + l16]);
            uint2 r = R2[p.y + l16];
            __half2 d0 = __hsub2(*reinterpret_cast<const __half2*>(&x.x),
                                 *reinterpret_cast<const __half2*>(&r.x));
            __half2 d1 = __hsub2(*reinterpret_cast<const __half2*>(&x.y),
                                 *reinterpret_cast<const __half2*>(&r.y));
            float2 f0 = __half22float2(d0);
            float2 f1 = __half22float2(d1);
            acc.x += f0.x; acc.y += f0.y;
            acc.z += f1.x; acc.w += f1.y;
        }
    }
    for (; i < deg; i += 2) {
        if (i + half < deg) {
            uint2 p = __ldcg(&pk2[i + half]);
            uint2 x = __ldcg(&X2[p.x + l16]);
            uint2 r = R2[p.y + l16];
            __half2 d0 = __hsub2(*reinterpret_cast<const __half2*>(&x.x),
                                 *reinterpret_cast<const __half2*>(&r.x));
            __half2 d1 = __hsub2(*reinterpret_cast<const __half2*>(&x.y),
                                 *reinterpret_cast<const __half2*>(&r.y));
            float2 f0 = __half22float2(d0);
            float2 f1 = __half22float2(d1);
            acc.x += f0.x; acc.y += f0.y;
            acc.z += f1.x; acc.w += f1.y;
        }
    }
    acc.x += __shfl_xor_sync(0xffffffffu, acc.x, 16);
    acc.y += __shfl_xor_sync(0xffffffffu, acc.y, 16);
    acc.z += __shfl_xor_sync(0xffffffffu, acc.z, 16);
    acc.w += __shfl_xor_sync(0xffffffffu, acc.w, 16);

    if (half == 0) {
        float inv = 1.0f / (float)(deg > 1 ? deg : 1);
        reinterpret_cast<float4*>(out)[(size_t)v * 16 + l16] =
            make_float4(acc.x * inv, acc.y * inv, acc.z * inv, acc.w * inv);
    }
    if (lane == 0) g_cnt[v] = 0;
}

// ---------------------------------------------------------------------------
extern "C" void kernel_launch(void* const* d_in, const int* in_sizes, int n_in,
                              void* d_out, int out_size) {
    const float* nf = (const float*)d_in[0];
    const float* rf = (const float*)d_in[1];
    const float* WI = (const float*)d_in[2];
    const float* bI = (const float*)d_in[3];
    const float* WO = (const float*)d_in[4];
    const float* bO = (const float*)d_in[5];
    const float* WR = (const float*)d_in[6];
    const float* bR = (const float*)d_in[7];
    const int* src  = (const int*)d_in[8];
    const int* dst  = (const int*)d_in[9];
    const int* et   = (const int*)d_in[10];
    const int* nrp  = (n_in > 11) ? (const int*)d_in[11] : nullptr;

    int Dv = in_sizes[3];            // = 64
    int N  = in_sizes[0] / Dv;
    int R  = in_sizes[1] / Dv;
    int E  = in_sizes[8];
    float* out = (float*)d_out;
    float* r_out = out + (size_t)N * Dv;

    int nbScan = (N + 255) / 256;
    int nbNT   = (N + 63) / 64;
    int nbH    = (E + 2047) / 2048;
    int nbRe   = (((E >> 2) + 1) + 255) / 256;

    static int attrSet = 0;
    if (!attrSet) {
        cudaFuncSetAttribute(k_mega, cudaFuncAttributeMaxDynamicSharedMemorySize,
                             FSMEM);
        attrSet = 1;
    }

    k_mega<<<nbH + nbScan + nbNT + R + nbRe, 256, FSMEM>>>(
        nf, rf, WI, bI, WO, bO, WR, bR, r_out,
        src, dst, et, nrp, E, N, R, R / 2, nbH, nbScan, nbNT);

    {
        long long threads = (long long)N * 32;
        k_gather<<<(int)((threads + 255) / 256), 256>>>(out, N);
    }
}

// round 12
// speedup vs baseline: 1.5844x; 1.0314x over previous
#include <cuda_runtime.h>
#include <cuda_fp16.h>
#include <mma.h>
#include <math.h>

using namespace nvcuda;

#define DD 64
#define MAXNB  256
#define MAXNPAD (MAXNB * 256)
#define MAXR 256
#define MAXE 2097152

// Scratch (static device globals — no allocation anywhere; BSS zero-initialized)
__device__ unsigned g_Xh[2 * 50176 * 32]; // half2 words; row = 32 half2 = 8 uint4
__device__ unsigned g_Rh[2 * MAXR * 32];
__device__ int   g_cnt[MAXNPAD];
__device__ int   g_lex[MAXNPAD];
__device__ int   g_bsum[MAXNB];
__device__ int   g_base[MAXNB];
__device__ int   g_rank[MAXE];
__device__ uint2 g_pack2[MAXE];           // (x_row*8, r_row*8) uint4 offsets, CSR order
__device__ int   g_scanDone;              // self-resetting
__device__ int   g_scanFlag;              // reset by gather
__device__ int   g_histDone;              // reset by gather

// smem: sB half[64][136] (17408B) + sA double buffer 2 x half[64][72] (18432B)
//       + per-warp f32 scratch 8 x 16x20 (10240B) = 46080B
#define LDA 72
#define LDB 136
#define LDW 20
#define SA_BYTES (64 * LDA * 2)
#define SB_BYTES (64 * LDB * 2)
#define FSMEM (SB_BYTES + 2 * SA_BYTES + 8 * 16 * LDW * 4)

// ---------------------------------------------------------------------------
// K1 mega: [GEMM][hist][scan][rel][reorder] in one launch, overlapped via
// dispatch-order + counter/flag handshakes (monotone block dispatch).
// ---------------------------------------------------------------------------
__global__ void __launch_bounds__(256, 3) k_mega(
    const float* __restrict__ nf, const float* __restrict__ rf,
    const float* __restrict__ WI, const float* __restrict__ bI,
    const float* __restrict__ WO, const float* __restrict__ bO,
    const float* __restrict__ WR, const float* __restrict__ bR,
    float* __restrict__ r_out,
    const int* __restrict__ src, const int* __restrict__ dst,
    const int* __restrict__ et, const int* __restrict__ nrp,
    int E, int N, int R, int halfFB,
    int nbNT, int nbH, int nbScan) {

    extern __shared__ __align__(16) unsigned char smem_raw[];
    __shared__ int s[256];
    __shared__ bool amLast;

    int b = blockIdx.x;
    int tid = threadIdx.x;

    // ================= phase 1: node-transform GEMM, 256 rows/block =================
    if (b < nbNT) {
        __half* sB  = reinterpret_cast<__half*>(smem_raw);               // [k][c] ld=LDB
        __half* sA0 = reinterpret_cast<__half*>(smem_raw + SB_BYTES);
        __half* sA1 = sA0 + 64 * LDA;
        float* scratchBase = reinterpret_cast<float*>(smem_raw + SB_BYTES + 2 * SA_BYTES);

        int rowBase = b * 256;

        // weights -> fp16 smem transposed, half2-packed (ONCE per 256 rows)
        for (int i = tid; i < 64 * 16; i += 256) {
            int cw2 = i & 63;
            int k4  = (i >> 6) * 4;
            const float* Wb = (cw2 < 32) ? WI : WO;
            int c0 = (cw2 & 31) * 2;
            float4 va = *reinterpret_cast<const float4*>(Wb + c0 * 64 + k4);
            float4 vb = *reinterpret_cast<const float4*>(Wb + (c0 + 1) * 64 + k4);
            *reinterpret_cast<__half2*>(&sB[(k4 + 0) * LDB + cw2 * 2]) = __floats2half2_rn(va.x, vb.x);
            *reinterpret_cast<__half2*>(&sB[(k4 + 1) * LDB + cw2 * 2]) = __floats2half2_rn(va.y, vb.y);
            *reinterpret_cast<__half2*>(&sB[(k4 + 2) * LDB + cw2 * 2]) = __floats2half2_rn(va.z, vb.z);
            *reinterpret_cast<__half2*>(&sB[(k4 + 3) * LDB + cw2 * 2]) = __floats2half2_rn(va.w, vb.w);
        }
        // first x tile direct
#pragma unroll
        for (int it = 0; it < 4; it++) {
            int i = tid + it * 256;
            int r  = i >> 4;
            int c4 = (i & 15) * 4;
            float4 v = make_float4(0.f, 0.f, 0.f, 0.f);
            int row = rowBase + r;
            if (row < N) v = *reinterpret_cast<const float4*>(nf + (size_t)row * 64 + c4);
            *reinterpret_cast<__half2*>(&sA0[r * LDA + c4])     = __floats2half2_rn(v.x, v.y);
            *reinterpret_cast<__half2*>(&sA0[r * LDA + c4 + 2]) = __floats2half2_rn(v.z, v.w);
        }
        __syncthreads();

        int w = tid >> 5;
        int lane = tid & 31;
        int rowT = w & 3;
        int colBase = (w >> 2) * 4;
        float* swarp = scratchBase + w * (16 * LDW);

#pragma unroll
        for (int t = 0; t < 4; t++) {
            __half* sAcur  = (t & 1) ? sA1 : sA0;
            __half* sAnext = (t & 1) ? sA0 : sA1;
            int row0 = rowBase + t * 64;

            // prefetch next tile into registers (hidden under mma+epilogue)
            float4 stage[4];
            if (t < 3) {
                int rowN0 = rowBase + (t + 1) * 64;
#pragma unroll
                for (int it = 0; it < 4; it++) {
                    int i = tid + it * 256;
                    int r  = i >> 4;
                    int c4 = (i & 15) * 4;
                    int row = rowN0 + r;
                    stage[it] = (row < N)
                        ? *reinterpret_cast<const float4*>(nf + (size_t)row * 64 + c4)
                        : make_float4(0.f, 0.f, 0.f, 0.f);
                }
            }

            // mma on current tile
            wmma::fragment<wmma::accumulator, 16, 16, 16, float> acc[4];
#pragma unroll
            for (int j = 0; j < 4; j++) wmma::fill_fragment(acc[j], 0.0f);
#pragma unroll
            for (int kt = 0; kt < 4; kt++) {
                wmma::fragment<wmma::matrix_a, 16, 16, 16, __half, wmma::row_major> fa;
                wmma::load_matrix_sync(fa, &sAcur[(rowT * 16) * LDA + kt * 16], LDA);
#pragma unroll
                for (int j = 0; j < 4; j++) {
                    wmma::fragment<wmma::matrix_b, 16, 16, 16, __half, wmma::row_major> fb;
                    wmma::load_matrix_sync(fb, &sB[(kt * 16) * LDB + (colBase + j) * 16], LDB);
                    wmma::mma_sync(acc[j], fa, fb, acc[j]);
                }
            }

            // warp-private epilogue
#pragma unroll
            for (int j = 0; j < 4; j++) {
                wmma::store_matrix_sync(swarp, acc[j], LDW, wmma::mem_row_major);
                __syncwarp();
                int c0w = (colBase + j) * 8;
                unsigned* dstBase = (c0w < 32)
                    ? g_Xh + c0w
                    : g_Xh + (size_t)N * 32 + (c0w - 32);
#pragma unroll
                for (int q = 0; q < 2; q++) {
                    int idx = lane + 32 * q;  // 0..63
                    int r   = idx >> 2;
                    int w2  = (idx & 3) * 2;
                    float4 f = *reinterpret_cast<const float4*>(&swarp[r * LDW + w2 * 2]);
                    int row = row0 + rowT * 16 + r;
                    if (row < N) {
                        __half2 h0 = __floats2half2_rn(f.x, f.y);
                        __half2 h1 = __floats2half2_rn(f.z, f.w);
                        uint2 hv = make_uint2(*reinterpret_cast<unsigned*>(&h0),
                                              *reinterpret_cast<unsigned*>(&h1));
                        *reinterpret_cast<uint2*>(dstBase + (size_t)row * 32 + w2) = hv;
                    }
                }
                __syncwarp();
            }

            if (t < 3) {
#pragma unroll
                for (int it = 0; it < 4; it++) {
                    int i = tid + it * 256;
                    int r  = i >> 4;
                    int c4 = (i & 15) * 4;
                    *reinterpret_cast<__half2*>(&sAnext[r * LDA + c4])     = __floats2half2_rn(stage[it].x, stage[it].y);
                    *reinterpret_cast<__half2*>(&sAnext[r * LDA + c4 + 2]) = __floats2half2_rn(stage[it].z, stage[it].w);
                }
                __syncthreads();
            }
        }
        return;
    }
    b -= nbNT;

    // ======================= phase 2: histogram + rank =======================
    if (b < nbH) {
        int t0 = (b * 256 + tid) * 8;
        if (t0 + 8 <= E) {
            int4 d0 = *reinterpret_cast<const int4*>(dst + t0);
            int4 d1 = *reinterpret_cast<const int4*>(dst + t0 + 4);
            int r0 = atomicAdd(&g_cnt[d0.x], 1);
            int r1 = atomicAdd(&g_cnt[d0.y], 1);
            int r2 = atomicAdd(&g_cnt[d0.z], 1);
            int r3 = atomicAdd(&g_cnt[d0.w], 1);
            int r4 = atomicAdd(&g_cnt[d1.x], 1);
            int r5 = atomicAdd(&g_cnt[d1.y], 1);
            int r6 = atomicAdd(&g_cnt[d1.z], 1);
            int r7 = atomicAdd(&g_cnt[d1.w], 1);
            *reinterpret_cast<int4*>(g_rank + t0)     = make_int4(r0, r1, r2, r3);
            *reinterpret_cast<int4*>(g_rank + t0 + 4) = make_int4(r4, r5, r6, r7);
        } else {
            for (int e = t0; e < E; e++)
                g_rank[e] = atomicAdd(&g_cnt[dst[e]], 1);
        }
        __threadfence();
        __syncthreads();
        if (tid == 0) atomicAdd(&g_histDone, 1);
        return;
    }
    b -= nbH;

    // ======================= phase 3: two-level scan =======================
    if (b < nbScan) {
        if (tid == 0) {
            while (atomicAdd(&g_histDone, 0) < nbH) __nanosleep(100);
        }
        __syncthreads();
        __threadfence();

        int i = b * 256 + tid;
        int v = g_cnt[i];
        s[tid] = v;
        __syncthreads();
#pragma unroll
        for (int off = 1; off < 256; off <<= 1) {
            int x = (tid >= off) ? s[tid - off] : 0;
            __syncthreads();
            s[tid] += x;
            __syncthreads();
        }
        g_lex[i] = s[tid] - v;
        if (tid == 255) g_bsum[b] = s[tid];
        __threadfence();
        if (tid == 0) {
            int d = atomicAdd(&g_scanDone, 1);
            amLast = (d == nbScan - 1);
        }
        __syncthreads();
        if (amLast) {
            __threadfence();
            int v2 = (tid < nbScan) ? g_bsum[tid] : 0;
            s[tid] = v2;
            __syncthreads();
#pragma unroll
            for (int off = 1; off < 256; off <<= 1) {
                int x = (tid >= off) ? s[tid - off] : 0;
                __syncthreads();
                s[tid] += x;
                __syncthreads();
            }
            if (tid < nbScan) g_base[tid] = s[tid] - v2;
            __threadfence();
            __syncthreads();
            if (tid == 0) {
                g_scanDone = 0;
                atomicExch(&g_scanFlag, 1);
            }
        }
        return;
    }
    b -= nbScan;

    // ======================= phase 4: relation tables =======================
    if (b < R) {
        float* sf = reinterpret_cast<float*>(smem_raw);
        int t = b, j = tid;
        if (j < DD) sf[j] = rf[t * DD + j];
        __syncthreads();
        if (j < DD) {
            float aI = 0.f, aO = 0.f, aR = 0.f;
#pragma unroll 8
            for (int k = 0; k < DD; k++) {
                float v = sf[k];
                aI += v * WI[j * DD + k];
                aO += v * WO[j * DD + k];
                aR += v * WR[j * DD + k];
            }
            __half* Rh = reinterpret_cast<__half*>(g_Rh);
            Rh[t * DD + j]          = __float2half_rn(aI - bI[j]);
            Rh[(MAXR + t) * DD + j] = __float2half_rn(aO - bO[j]);
            r_out[t * DD + j]       = aR + bR[j];
        }
        return;
    }
    b -= R;

    // ======================= phase 5: CSR reorder =======================
    {
        int i = b * 256 + tid;
        int half = nrp ? (__ldg(nrp) >> 1) : halfFB;
        int main4 = E >> 2;

        int4 s4, d4, t4;
        bool haveMain = (i < main4);
        if (haveMain) {
            s4 = reinterpret_cast<const int4*>(src)[i];
            d4 = reinterpret_cast<const int4*>(dst)[i];
            t4 = reinterpret_cast<const int4*>(et)[i];
        }

        if (tid == 0) {
            while (atomicAdd(&g_scanFlag, 0) == 0) __nanosleep(200);
        }
        __syncthreads();
        __threadfence();   // acquire: g_base/g_lex/g_rank now visible

        if (haveMain) {
            int4 r4 = reinterpret_cast<const int4*>(g_rank)[i];
#pragma unroll
            for (int u = 0; u < 4; u++) {
                int ss = (u == 0) ? s4.x : (u == 1) ? s4.y : (u == 2) ? s4.z : s4.w;
                int dd = (u == 0) ? d4.x : (u == 1) ? d4.y : (u == 2) ? d4.z : d4.w;
                int tt = (u == 0) ? t4.x : (u == 1) ? t4.y : (u == 2) ? t4.z : t4.w;
                int rr = (u == 0) ? r4.x : (u == 1) ? r4.y : (u == 2) ? r4.z : r4.w;
                int pos = g_base[dd >> 8] + g_lex[dd] + rr;
                unsigned row, trow;
                if (tt < half) { row = (unsigned)ss;       trow = (unsigned)tt; }
                else           { row = (unsigned)(ss + N); trow = (unsigned)(tt + MAXR); }
                g_pack2[pos] = make_uint2(row * 8u, trow * 8u);
            }
        } else if (i == main4) {
            for (int e = main4 * 4; e < E; e++) {
                int ss = src[e], dd = dst[e], tt = et[e], rr = g_rank[e];
                int pos = g_base[dd >> 8] + g_lex[dd] + rr;
                unsigned row, trow;
                if (tt < half) { row = (unsigned)ss;       trow = (unsigned)tt; }
                else           { row = (unsigned)(ss + N); trow = (unsigned)(tt + MAXR); }
                g_pack2[pos] = make_uint2(row * 8u, trow * 8u);
            }
        }
    }
}

// ---------------------------------------------------------------------------
// K2: gather + mean. 1 warp/node, 4 edges per wave (8 lanes x uint4 fp16).
// fp16 HSUB2 diff, fp32 accumulate, quarter-reduction at the end.
// Resets histDone/scanFlag/g_cnt for the next replay.
// ---------------------------------------------------------------------------
__global__ void __launch_bounds__(256) k_gather(float* __restrict__ out, int N) {
    int gid = blockIdx.x * 256 + threadIdx.x;
    if (gid == 0) { g_scanFlag = 0; g_histDone = 0; }
    int v = gid >> 5;
    if (v >= N) return;
    int lane = threadIdx.x & 31;
    int q  = lane >> 3;      // edge within wave
    int l8 = lane & 7;       // uint4 within row

    int start = g_base[v >> 8] + g_lex[v];
    int deg   = g_cnt[v];

    const uint2* __restrict__ pk2 = g_pack2 + start;
    const uint4* __restrict__ X4 = reinterpret_cast<const uint4*>(g_Xh);
    const uint4* __restrict__ R4 = reinterpret_cast<const uint4*>(g_Rh);

    float acc[8];
#pragma unroll
    for (int j = 0; j < 8; j++) acc[j] = 0.f;

    int i = 0;
    for (; i + 8 <= deg; i += 8) {
#pragma unroll
        for (int u = 0; u < 2; u++) {
            uint2 p = __ldcg(&pk2[i + 4 * u + q]);
            uint4 x = __ldcg(&X4[p.x + l8]);
            uint4 r = R4[p.y + l8];
            __half2 d0 = __hsub2(*reinterpret_cast<const __half2*>(&x.x),
                                 *reinterpret_cast<const __half2*>(&r.x));
            __half2 d1 = __hsub2(*reinterpret_cast<const __half2*>(&x.y),
                                 *reinterpret_cast<const __half2*>(&r.y));
            __half2 d2 = __hsub2(*reinterpret_cast<const __half2*>(&x.z),
                                 *reinterpret_cast<const __half2*>(&r.z));
            __half2 d3 = __hsub2(*reinterpret_cast<const __half2*>(&x.w),
                                 *reinterpret_cast<const __half2*>(&r.w));
            float2 f0 = __half22float2(d0);
            float2 f1 = __half22float2(d1);
            float2 f2 = __half22float2(d2);
            float2 f3 = __half22float2(d3);
            acc[0] += f0.x; acc[1] += f0.y;
            acc[2] += f1.x; acc[3] += f1.y;
            acc[4] += f2.x; acc[5] += f2.y;
            acc[6] += f3.x; acc[7] += f3.y;
        }
    }
    for (; i < deg; i += 4) {
        if (i + q < deg) {
            uint2 p = __ldcg(&pk2[i + q]);
            uint4 x = __ldcg(&X4[p.x + l8]);
            uint4 r = R4[p.y + l8];
            __half2 d0 = __hsub2(*reinterpret_cast<const __half2*>(&x.x),
                                 *reinterpret_cast<const __half2*>(&r.x));
            __half2 d1 = __hsub2(*reinterpret_cast<const __half2*>(&x.y),
                                 *reinterpret_cast<const __half2*>(&r.y));
            __half2 d2 = __hsub2(*reinterpret_cast<const __half2*>(&x.z),
                                 *reinterpret_cast<const __half2*>(&r.z));
            __half2 d3 = __hsub2(*reinterpret_cast<const __half2*>(&x.w),
                                 *reinterpret_cast<const __half2*>(&r.w));
            float2 f0 = __half22float2(d0);
            float2 f1 = __half22float2(d1);
            float2 f2 = __half22float2(d2);
            float2 f3 = __half22float2(d3);
            acc[0] += f0.x; acc[1] += f0.y;
            acc[2] += f1.x; acc[3] += f1.y;
            acc[4] += f2.x; acc[5] += f2.y;
            acc[6] += f3.x; acc[7] += f3.y;
        }
    }

    // reduce the 4 quarter-warps (same column segment at lanes l8, l8+8, +16, +24)
#pragma unroll
    for (int j = 0; j < 8; j++) {
        acc[j] += __shfl_xor_sync(0xffffffffu, acc[j], 8);
        acc[j] += __shfl_xor_sync(0xffffffffu, acc[j], 16);
    }

    if (lane < 8) {
        float inv = 1.0f / (float)(deg > 1 ? deg : 1);
        float4* o = reinterpret_cast<float4*>(out + (size_t)v * 64 + l8 * 8);
        o[0] = make_float4(acc[0] * inv, acc[1] * inv, acc[2] * inv, acc[3] * inv);
        o[1] = make_float4(acc[4] * inv, acc[5] * inv, acc[6] * inv, acc[7] * inv);
    }
    if (lane == 0) g_cnt[v] = 0;
}

// ---------------------------------------------------------------------------
extern "C" void kernel_launch(void* const* d_in, const int* in_sizes, int n_in,
                              void* d_out, int out_size) {
    const float* nf = (const float*)d_in[0];
    const float* rf = (const float*)d_in[1];
    const float* WI = (const float*)d_in[2];
    const float* bI = (const float*)d_in[3];
    const float* WO = (const float*)d_in[4];
    const float* bO = (const float*)d_in[5];
    const float* WR = (const float*)d_in[6];
    const float* bR = (const float*)d_in[7];
    const int* src  = (const int*)d_in[8];
    const int* dst  = (const int*)d_in[9];
    const int* et   = (const int*)d_in[10];
    const int* nrp  = (n_in > 11) ? (const int*)d_in[11] : nullptr;

    int Dv = in_sizes[3];            // = 64
    int N  = in_sizes[0] / Dv;
    int R  = in_sizes[1] / Dv;
    int E  = in_sizes[8];
    float* out = (float*)d_out;
    float* r_out = out + (size_t)N * Dv;

    int nbScan = (N + 255) / 256;
    int nbNT   = (N + 255) / 256;    // 256 rows per GEMM block
    int nbH    = (E + 2047) / 2048;
    int nbRe   = (((E >> 2) + 1) + 255) / 256;

    static int attrSet = 0;
    if (!attrSet) {
        cudaFuncSetAttribute(k_mega, cudaFuncAttributeMaxDynamicSharedMemorySize,
                             FSMEM);
        attrSet = 1;
    }

    k_mega<<<nbNT + nbH + nbScan + R + nbRe, 256, FSMEM>>>(
        nf, rf, WI, bI, WO, bO, WR, bR, r_out,
        src, dst, et, nrp, E, N, R, R / 2, nbNT, nbH, nbScan);

    {
        long long threads = (long long)N * 32;
        k_gather<<<(int)((threads + 255) / 256), 256>>>(out, N);
    }
}